// round 12
// baseline (speedup 1.0000x reference)
#include <cuda_runtime.h>
#include <cuda_bf16.h>
#include <math.h>
#include <stdint.h>

#define NTOT 1024
#define NI   64
#define NC   960
#define NR   896
#define WARM 25
#define FULL 0xffffffffu

// ---------------- device scratch ----------------
__device__ __align__(16) __nv_bfloat16 g_Bh[NC * 64];
__device__ __align__(16) __nv_bfloat16 g_Bl[NC * 64];
__device__ __align__(16) float g_Ep[NR], g_Em[NR], g_Ip[NR], g_Im[NR];
__device__ __align__(16) int   g_pidx_e[NR], g_pidx_i[NR];
__device__ __align__(16) int   g_pos_e[NC], g_pos_i[NC];
__device__ __align__(16) float g_Tp[NC], g_Tm[NC], g_ctop[NC];
__device__ __align__(16) float g_base[NC];

__device__ __forceinline__ uint32_t smem_u32(const void* p) {
    uint32_t a;
    asm("{ .reg .u64 t; cvta.to.shared.u64 t, %1; cvt.u32.u64 %0, t; }" : "=r"(a) : "l"(p));
    return a;
}
#define SW128(x) ((x) ^ (((x) >> 3) & 0x70))

#define LDSM_X4(r0, r1, r2, r3, a) \
    asm volatile("ldmatrix.sync.aligned.m8n8.x4.shared.b16 {%0,%1,%2,%3}, [%4];" \
        : "=r"(r0), "=r"(r1), "=r"(r2), "=r"(r3) : "r"(a))

#define MMA16816(d, a, b0, b1) \
    asm volatile("mma.sync.aligned.m16n8k16.row.col.f32.bf16.bf16.f32 " \
        "{%0,%1,%2,%3}, {%4,%5,%6,%7}, {%8,%9}, {%0,%1,%2,%3};" \
        : "+f"((d)[0]), "+f"((d)[1]), "+f"((d)[2]), "+f"((d)[3]) \
        : "r"((a)[0]), "r"((a)[1]), "r"((a)[2]), "r"((a)[3]), "r"(b0), "r"(b1))

// =================== k_init: R7-exact ===================
__global__ void k_init(const float* __restrict__ ident, const float* __restrict__ enh,
                       const float* __restrict__ inh,  const float* __restrict__ beta) {
    const int b = blockIdx.x, t = threadIdx.x;
    const int wid = t >> 5, lane = t & 31;
    const float bb = beta[0];

    if (b < 240) {
        int idx = b * 256 + t;
        int j = idx >> 6, k = idx & 63;
        float id = ident[NI + j];
        float v = expf(-bb * fabsf(enh[k] - id)) - expf(-bb * fabsf(inh[k] - id));
        __nv_bfloat16 h = __float2bfloat16(v);
        __nv_bfloat16 l = __float2bfloat16(v - __bfloat162float(h));
        g_Bh[idx] = h;
        g_Bl[idx] = l;
    } else if (b < 464) {
        bool is_e = (b < 352);
        const float* arr = is_e ? enh : inh;
        int k = ((b - (is_e ? 240 : 352)) * 8 + wid);
        float x = arr[128 + k];
        int cnt = 0;
        for (int k2 = lane; k2 < NR; k2 += 32) {
            float y = arr[128 + k2];
            cnt += (y < x) || (y == x && k2 < k);
        }
        #pragma unroll
        for (int o = 16; o; o >>= 1) cnt += __shfl_xor_sync(FULL, cnt, o);
        if (lane == 0) {
            if (is_e) { g_pidx_e[cnt] = k; g_Ep[cnt] = expf(bb * x); g_Em[cnt] = expf(-bb * x); }
            else      { g_pidx_i[cnt] = k; g_Ip[cnt] = expf(bb * x); g_Im[cnt] = expf(-bb * x); }
        }
    } else if (b < 704) {
        bool is_e = (b < 584);
        const float* arr = is_e ? enh : inh;
        int j = ((b - (is_e ? 464 : 584)) * 8 + wid);
        float tj = ident[NI + j];
        int cnt = 0;
        for (int k2 = lane; k2 < NR; k2 += 32) cnt += (arr[128 + k2] <= tj);
        #pragma unroll
        for (int o = 16; o; o >>= 1) cnt += __shfl_xor_sync(FULL, cnt, o);
        if (lane == 0) { if (is_e) g_pos_e[j] = cnt; else g_pos_i[j] = cnt; }
    } else if (b < 824) {
        int j = (b - 704) * 8 + wid;
        float tj = ident[NI + j];
        float c = 0.0f;
        for (int k = lane; k < NI; k += 32)
            c += expf(-bb * fabsf(enh[k] - tj)) - expf(-bb * fabsf(inh[k] - tj));
        #pragma unroll
        for (int o = 16; o; o >>= 1) c += __shfl_xor_sync(FULL, c, o);
        if (lane == 0) g_ctop[j] = c;
    } else {
        int j = (b - 824) * 256 + t;
        if (j < NC) {
            float tj = ident[NI + j];
            g_Tp[j] = expf(bb * tj);
            g_Tm[j] = expf(-bb * tj);
        }
    }
}

// =================== k_warm: R8 3-sync scan body ===================
__global__ void __launch_bounds__(1024, 1) k_warm(const float* __restrict__ delta) {
    __shared__ float rA[NC], rB[NC];
    __shared__ __align__(16) float SPe[NR], SQe[NR], SPi[NR], SQi[NR];
    __shared__ float2 wt2[16];
    __shared__ __align__(16) float wsum[32];
    const int t = threadIdx.x, lane = t & 31, warp = t >> 5;

    const bool role_e = (t < 224);
    const bool role_i = (t >= 256 && t < 480);
    const bool scanner = role_e || role_i;
    const int seg = role_e ? t : (t - 256);
    const int w0  = role_e ? 0 : 8;

    int4 px = make_int4(0, 0, 0, 0);
    float4 Pp = make_float4(0, 0, 0, 0), Pm = Pp;
    if (role_e) {
        px = ((const int4*)g_pidx_e)[seg];
        Pp = ((const float4*)g_Ep)[seg];
        Pm = ((const float4*)g_Em)[seg];
    } else if (role_i) {
        px = ((const int4*)g_pidx_i)[seg];
        Pp = ((const float4*)g_Ip)[seg];
        Pm = ((const float4*)g_Im)[seg];
    }
    px.x += 64; px.y += 64; px.z += 64; px.w += 64;

    float Tp = 0, Tm = 0, ct = 0; int poe = 0, poi = 0;
    if (t < NC) { Tp = g_Tp[t]; Tm = g_Tm[t]; ct = g_ctop[t];
                  poe = g_pos_e[t]; poi = g_pos_i[t];
                  rA[t] = 1.0f / (float)NTOT; }
    float s = 1.0f;
    const float d = delta[0];
    __syncthreads();
    float *rc = rA, *rn = rB;

    for (int it = 0; it <= WARM; it++) {
        float inv = (s > 0.0f) ? 1.0f / s : 1.0f;

        float sP[4], sQ[4], eP = 0, eQ = 0;
        if (scanner) {
            float r0 = rc[px.x], r1 = rc[px.y], r2 = rc[px.z], r3 = rc[px.w];
            sP[0] = r0 * Pp.x;          sQ[0] = r0 * Pm.x;
            sP[1] = sP[0] + r1 * Pp.y;  sQ[1] = sQ[0] + r1 * Pm.y;
            sP[2] = sP[1] + r2 * Pp.z;  sQ[2] = sQ[1] + r2 * Pm.z;
            sP[3] = sP[2] + r3 * Pp.w;  sQ[3] = sQ[2] + r3 * Pm.w;
            float iP = sP[3], iQ = sQ[3];
            #pragma unroll
            for (int o = 1; o < 32; o <<= 1) {
                float bP = __shfl_up_sync(FULL, iP, o);
                float bQ = __shfl_up_sync(FULL, iQ, o);
                if (lane >= o) { iP += bP; iQ += bQ; }
            }
            eP = iP - sP[3];  eQ = iQ - sQ[3];
            if (lane == 31) wt2[warp] = make_float2(iP, iQ);
        }
        __syncthreads();                                   // (1)

        if (scanner) {
            int wl = warp - w0;
            float bP = eP, bQ = eQ;
            #pragma unroll 6
            for (int w = 0; w < wl; w++) { float2 v = wt2[w0 + w]; bP += v.x; bQ += v.y; }
            float* SP = role_e ? SPe : SPi;
            float* SQ = role_e ? SQe : SQi;
            ((float4*)SP)[seg] = make_float4(bP + sP[0], bP + sP[1], bP + sP[2], bP + sP[3]);
            ((float4*)SQ)[seg] = make_float4(bQ + sQ[0], bQ + sQ[1], bQ + sQ[2], bQ + sQ[3]);
        }
        __syncthreads();                                   // (2)

        float nv = 0.0f;
        if (t < NC) {
            float tot1 = 0.0f, tot3 = 0.0f;
            #pragma unroll
            for (int w = 0; w < 7; w++) { tot1 += wt2[w].y; tot3 += wt2[8 + w].y; }
            float spe = poe ? SPe[poe - 1] : 0.0f;
            float sqe = poe ? SQe[poe - 1] : 0.0f;
            float spi = poi ? SPi[poi - 1] : 0.0f;
            float sqi = poi ? SQi[poi - 1] : 0.0f;
            float de  = Tm * spe + Tp * (tot1 - sqe);
            float di  = Tm * spi + Tp * (tot3 - sqi);
            float dot = (de - di) * inv;
            float conc = rc[t] * inv;
            if (it < WARM) {
                float dc = (d / (float)NTOT) * (ct * (1.0f / (float)NTOT) + dot);
                nv = fmaxf(conc + dc, 0.0f);
                rn[t] = nv;
            } else {
                g_base[t] = conc + (d / (float)NTOT) * dot;
            }
        }
        if (it == WARM) break;

        #pragma unroll
        for (int o = 16; o; o >>= 1) nv += __shfl_xor_sync(FULL, nv, o);
        if (lane == 0) wsum[warp] = nv;
        __syncthreads();                                   // (3)

        float acc = 0.0f;
        #pragma unroll
        for (int q = 0; q < 8; q++) {
            float4 v = ((const float4*)wsum)[q];
            acc += (v.x + v.y) + (v.z + v.w);
        }
        s = acc;
        float* tmp = rc; rc = rn; rn = tmp;
    }
}

// =================== k_gemm: 64-row tiles, 2 CTAs/SM, reg-prefetch B ========
#define SMA_H   0                  // 64 rows x 128B
#define SMA_L   8192
#define SMB_H   16384              // 64 rows x 128B
#define SMB_L   24576
#define SMBASE  32768              // 960 floats
#define SMRSUM  (SMBASE + 3840)    // 64 rows x 2 halves
#define SMTOT   (SMRSUM + 512)

__global__ void __launch_bounds__(256, 2)
k_gemm(const float* __restrict__ X, const float* __restrict__ delta,
       float* __restrict__ out) {
    extern __shared__ char sm[];
    const uint32_t sb = smem_u32(sm);
    float* sbase = (float*)(sm + SMBASE);
    float* srsum = (float*)(sm + SMRSUM);
    const int tid = threadIdx.x, wid = tid >> 5, lane = tid & 31;
    const int gr = lane >> 2, tg = lane & 3;
    const int r0 = blockIdx.x * 64;
    const int rg = wid >> 1;
    const int cg = wid & 1;
    const int m0 = rg * 16;

    // per-thread B staging indices (constant across chunks)
    const int bf_isl = tid >> 7;                 // with q*256: recomputed below
    (void)bf_isl;

    // issue chunk-0 B loads first (overlap with A conversion)
    uint4 rb[4];
    #pragma unroll
    for (int q = 0; q < 4; q++) {
        int f = q * 256 + tid;
        int isl = f >> 9;
        int r  = (f & 511) >> 3, ch = f & 7;
        const uint4* src = isl ? (const uint4*)g_Bl : (const uint4*)g_Bh;
        rb[q] = src[(size_t)r * 8 + ch];
    }

    for (int i = tid; i < NC; i += 256) sbase[i] = g_base[i];

    // A tile: 64x64 fp32 -> bf16 hi/lo, SW128 swizzled
    for (int i = tid; i < 2048; i += 256) {
        int m = i >> 5, c2 = i & 31;
        float2 x = *(const float2*)(X + (size_t)(r0 + m) * 64 + 2 * c2);
        __nv_bfloat162 hp = __floats2bfloat162_rn(x.x, x.y);
        float2 hf = __bfloat1622float2(hp);
        __nv_bfloat162 lp = __floats2bfloat162_rn(x.x - hf.x, x.y - hf.y);
        uint32_t off = SW128((uint32_t)(m * 128 + c2 * 4));
        *(uint32_t*)(sm + SMA_H + off) = *(uint32_t*)&hp;
        *(uint32_t*)(sm + SMA_L + off) = *(uint32_t*)&lp;
    }

    // store chunk 0 B into smem
    #pragma unroll
    for (int q = 0; q < 4; q++) {
        int f = q * 256 + tid;
        int isl = f >> 9;
        int r  = (f & 511) >> 3, ch = f & 7;
        uint32_t off = SW128((uint32_t)(r * 128 + ch * 16));
        *(uint4*)(sm + (isl ? SMB_L : SMB_H) + off) = rb[q];
    }
    __syncthreads();

    // chunk-invariant A fragments
    uint32_t ah[4][4], al[4][4];
    {
        int arow = m0 + (lane & 7) + ((lane >> 3) & 1) * 8;
        int acol = (lane >> 4) & 1;
        #pragma unroll
        for (int ks = 0; ks < 4; ks++) {
            uint32_t off = SW128((uint32_t)(arow * 128 + (ks * 2 + acol) * 16));
            LDSM_X4(ah[ks][0], ah[ks][1], ah[ks][2], ah[ks][3], sb + SMA_H + off);
            LDSM_X4(al[ks][0], al[ks][1], al[ks][2], al[ks][3], sb + SMA_L + off);
        }
    }

    const float sc = delta[0] / (float)NTOT;
    float rsLo = 0.0f, rsHi = 0.0f;
    float2 vlo[4], vhi[4];

    const int brow_off = (lane & 7) + ((lane >> 4) & 1) * 8;
    const int bcol_off = (lane >> 3) & 1;

    for (int cc = 0; cc < 15; cc++) {
        // prefetch next chunk into registers (LDG issues now, consumed later)
        if (cc < 14) {
            #pragma unroll
            for (int q = 0; q < 4; q++) {
                int f = q * 256 + tid;
                int isl = f >> 9;
                int r  = (f & 511) >> 3, ch = f & 7;
                const uint4* src = isl ? (const uint4*)g_Bl : (const uint4*)g_Bh;
                rb[q] = src[(size_t)((cc + 1) * 64 + r) * 8 + ch];
            }
        }

        float dacc[4][4];
        #pragma unroll
        for (int nt = 0; nt < 4; nt++)
            #pragma unroll
            for (int r = 0; r < 4; r++) dacc[nt][r] = 0.0f;

        #pragma unroll
        for (int ks = 0; ks < 4; ks++) {
            #pragma unroll
            for (int npl = 0; npl < 2; npl++) {
                int np = cg * 2 + npl;
                uint32_t boff = SW128((uint32_t)((np * 16 + brow_off) * 128 +
                                                 (ks * 2 + bcol_off) * 16));
                uint32_t b0, b1, b2, b3;
                LDSM_X4(b0, b1, b2, b3, sb + SMB_H + boff);
                MMA16816(dacc[npl * 2],     ah[ks], b0, b1);
                MMA16816(dacc[npl * 2 + 1], ah[ks], b2, b3);
                MMA16816(dacc[npl * 2],     al[ks], b0, b1);
                MMA16816(dacc[npl * 2 + 1], al[ks], b2, b3);
                LDSM_X4(b0, b1, b2, b3, sb + SMB_L + boff);
                MMA16816(dacc[npl * 2],     ah[ks], b0, b1);
                MMA16816(dacc[npl * 2 + 1], ah[ks], b2, b3);
            }
        }

        // epilogue: base + relu + row-sum partials
        #pragma unroll
        for (int nt = 0; nt < 4; nt++) {
            float2 bb = *(const float2*)(sbase + cc * 64 + cg * 32 + nt * 8 + tg * 2);
            float v00 = fmaxf(bb.x + sc * dacc[nt][0], 0.0f);
            float v01 = fmaxf(bb.y + sc * dacc[nt][1], 0.0f);
            float v10 = fmaxf(bb.x + sc * dacc[nt][2], 0.0f);
            float v11 = fmaxf(bb.y + sc * dacc[nt][3], 0.0f);
            rsLo += v00 + v01;
            rsHi += v10 + v11;
            if (cc == 0) { vlo[nt] = make_float2(v00, v01);
                           vhi[nt] = make_float2(v10, v11); }
        }
        __syncthreads();            // everyone done READING this chunk's smem

        if (cc < 14) {              // store prefetched chunk, then publish
            #pragma unroll
            for (int q = 0; q < 4; q++) {
                int f = q * 256 + tid;
                int isl = f >> 9;
                int r  = (f & 511) >> 3, ch = f & 7;
                uint32_t off = SW128((uint32_t)(r * 128 + ch * 16));
                *(uint4*)(sm + (isl ? SMB_L : SMB_H) + off) = rb[q];
            }
            __syncthreads();
        }
    }

    // row sums: quad-reduce, cross-warp combine of the 2 col halves
    rsLo += __shfl_xor_sync(FULL, rsLo, 1);
    rsLo += __shfl_xor_sync(FULL, rsLo, 2);
    rsHi += __shfl_xor_sync(FULL, rsHi, 1);
    rsHi += __shfl_xor_sync(FULL, rsHi, 2);
    if (tg == 0) {
        srsum[(m0 + gr) * 2 + cg]     = rsLo;
        srsum[(m0 + gr + 8) * 2 + cg] = rsHi;
    }
    __syncthreads();

    int rowLo = m0 + gr, rowHi = rowLo + 8;
    float tLo = srsum[rowLo * 2] + srsum[rowLo * 2 + 1];
    float tHi = srsum[rowHi * 2] + srsum[rowHi * 2 + 1];
    float invLo = (tLo > 0.0f) ? 1.0f / tLo : 1.0f;
    float invHi = (tHi > 0.0f) ? 1.0f / tHi : 1.0f;

    #pragma unroll
    for (int nt = 0; nt < 4; nt++) {
        int c = cg * 32 + nt * 8 + tg * 2;
        *(float2*)(out + (size_t)(r0 + rowLo) * 64 + c) =
            make_float2(vlo[nt].x * invLo, vlo[nt].y * invLo);
        *(float2*)(out + (size_t)(r0 + rowHi) * 64 + c) =
            make_float2(vhi[nt].x * invHi, vhi[nt].y * invHi);
    }
}

// ---------------- launch ----------------
extern "C" void kernel_launch(void* const* d_in, const int* in_sizes, int n_in,
                              void* d_out, int out_size) {
    const float* inputs      = (const float*)d_in[0];
    const float* identifiers = (const float*)d_in[1];
    const float* enhancers   = (const float*)d_in[2];
    const float* inhibitors  = (const float*)d_in[3];
    const float* beta        = (const float*)d_in[4];
    const float* delta       = (const float*)d_in[5];
    (void)in_sizes; (void)n_in; (void)out_size;

    cudaFuncSetAttribute(k_gemm, cudaFuncAttributeMaxDynamicSharedMemorySize, SMTOT);

    k_init<<<828, 256>>>(identifiers, enhancers, inhibitors, beta);
    k_warm<<<1, 1024>>>(delta);
    k_gemm<<<256, 256, SMTOT>>>(inputs, delta, (float*)d_out);
}

// round 13
// speedup vs baseline: 1.0694x; 1.0694x over previous
#include <cuda_runtime.h>
#include <cuda_bf16.h>
#include <math.h>
#include <stdint.h>

#define NTOT 1024
#define NI   64
#define NC   960
#define NR   896
#define WARM 25
#define FULL 0xffffffffu

// ---------------- device scratch ----------------
__device__ __align__(16) __nv_bfloat16 g_Bh[NC * 64];
__device__ __align__(16) __nv_bfloat16 g_Bl[NC * 64];
__device__ __align__(16) float g_Ep[NR], g_Em[NR], g_Ip[NR], g_Im[NR];
__device__ __align__(16) int   g_pidx_e[NR], g_pidx_i[NR];
__device__ __align__(16) int   g_pos_e[NC], g_pos_i[NC];
__device__ __align__(16) float g_Tp[NC], g_Tm[NC], g_ctop[NC];
__device__ __align__(16) float g_base[NC];

__device__ __forceinline__ uint32_t smem_u32(const void* p) {
    uint32_t a;
    asm("{ .reg .u64 t; cvta.to.shared.u64 t, %1; cvt.u32.u64 %0, t; }" : "=r"(a) : "l"(p));
    return a;
}
#define SW128(x) ((x) ^ (((x) >> 3) & 0x70))

#define LDSM_X4(r0, r1, r2, r3, a) \
    asm volatile("ldmatrix.sync.aligned.m8n8.x4.shared.b16 {%0,%1,%2,%3}, [%4];" \
        : "=r"(r0), "=r"(r1), "=r"(r2), "=r"(r3) : "r"(a))

#define MMA16816(d, a, b0, b1) \
    asm volatile("mma.sync.aligned.m16n8k16.row.col.f32.bf16.bf16.f32 " \
        "{%0,%1,%2,%3}, {%4,%5,%6,%7}, {%8,%9}, {%0,%1,%2,%3};" \
        : "+f"((d)[0]), "+f"((d)[1]), "+f"((d)[2]), "+f"((d)[3]) \
        : "r"((a)[0]), "r"((a)[1]), "r"((a)[2]), "r"((a)[3]), "r"(b0), "r"(b1))

// =================== k_init: R7-exact ===================
__global__ void k_init(const float* __restrict__ ident, const float* __restrict__ enh,
                       const float* __restrict__ inh,  const float* __restrict__ beta) {
    const int b = blockIdx.x, t = threadIdx.x;
    const int wid = t >> 5, lane = t & 31;
    const float bb = beta[0];

    if (b < 240) {
        int idx = b * 256 + t;
        int j = idx >> 6, k = idx & 63;
        float id = ident[NI + j];
        float v = expf(-bb * fabsf(enh[k] - id)) - expf(-bb * fabsf(inh[k] - id));
        __nv_bfloat16 h = __float2bfloat16(v);
        __nv_bfloat16 l = __float2bfloat16(v - __bfloat162float(h));
        g_Bh[idx] = h;
        g_Bl[idx] = l;
    } else if (b < 464) {
        bool is_e = (b < 352);
        const float* arr = is_e ? enh : inh;
        int k = ((b - (is_e ? 240 : 352)) * 8 + wid);
        float x = arr[128 + k];
        int cnt = 0;
        for (int k2 = lane; k2 < NR; k2 += 32) {
            float y = arr[128 + k2];
            cnt += (y < x) || (y == x && k2 < k);
        }
        #pragma unroll
        for (int o = 16; o; o >>= 1) cnt += __shfl_xor_sync(FULL, cnt, o);
        if (lane == 0) {
            if (is_e) { g_pidx_e[cnt] = k; g_Ep[cnt] = expf(bb * x); g_Em[cnt] = expf(-bb * x); }
            else      { g_pidx_i[cnt] = k; g_Ip[cnt] = expf(bb * x); g_Im[cnt] = expf(-bb * x); }
        }
    } else if (b < 704) {
        bool is_e = (b < 584);
        const float* arr = is_e ? enh : inh;
        int j = ((b - (is_e ? 464 : 584)) * 8 + wid);
        float tj = ident[NI + j];
        int cnt = 0;
        for (int k2 = lane; k2 < NR; k2 += 32) cnt += (arr[128 + k2] <= tj);
        #pragma unroll
        for (int o = 16; o; o >>= 1) cnt += __shfl_xor_sync(FULL, cnt, o);
        if (lane == 0) { if (is_e) g_pos_e[j] = cnt; else g_pos_i[j] = cnt; }
    } else if (b < 824) {
        int j = (b - 704) * 8 + wid;
        float tj = ident[NI + j];
        float c = 0.0f;
        for (int k = lane; k < NI; k += 32)
            c += expf(-bb * fabsf(enh[k] - tj)) - expf(-bb * fabsf(inh[k] - tj));
        #pragma unroll
        for (int o = 16; o; o >>= 1) c += __shfl_xor_sync(FULL, c, o);
        if (lane == 0) g_ctop[j] = c;
    } else {
        int j = (b - 824) * 256 + t;
        if (j < NC) {
            float tj = ident[NI + j];
            g_Tp[j] = expf(bb * tj);
            g_Tm[j] = expf(-bb * tj);
        }
    }
}

// =================== k_warm: R7-exact ===================
__global__ void __launch_bounds__(1024, 1) k_warm(const float* __restrict__ delta) {
    __shared__ float rA[NC], rB[NC];
    __shared__ __align__(16) float SPe[NR], SQe[NR], SPi[NR], SQi[NR];
    __shared__ float2 wt2[16];
    __shared__ float wsum[32];
    __shared__ float tot1, tot3, s_sh;
    const int t = threadIdx.x, lane = t & 31, warp = t >> 5;

    const bool role_e = (t < 224);
    const bool role_i = (t >= 256 && t < 480);
    const bool scanner = role_e || role_i;
    const int seg = role_e ? t : (t - 256);
    const int w0  = role_e ? 0 : 8;

    int4 px = make_int4(0, 0, 0, 0);
    float4 Pp = make_float4(0, 0, 0, 0), Pm = Pp;
    if (role_e) {
        px = ((const int4*)g_pidx_e)[seg];
        Pp = ((const float4*)g_Ep)[seg];
        Pm = ((const float4*)g_Em)[seg];
    } else if (role_i) {
        px = ((const int4*)g_pidx_i)[seg];
        Pp = ((const float4*)g_Ip)[seg];
        Pm = ((const float4*)g_Im)[seg];
    }
    px.x += 64; px.y += 64; px.z += 64; px.w += 64;

    float Tp = 0, Tm = 0, ct = 0; int poe = 0, poi = 0;
    if (t < NC) { Tp = g_Tp[t]; Tm = g_Tm[t]; ct = g_ctop[t];
                  poe = g_pos_e[t]; poi = g_pos_i[t];
                  rA[t] = 1.0f / (float)NTOT; }
    float s = 1.0f;
    const float d = delta[0];
    __syncthreads();
    float *rc = rA, *rn = rB;

    for (int it = 0; it <= WARM; it++) {
        float inv = (s > 0.0f) ? 1.0f / s : 1.0f;

        float sP[4], sQ[4], eP = 0, eQ = 0;
        if (scanner) {
            float r0 = rc[px.x], r1 = rc[px.y], r2 = rc[px.z], r3 = rc[px.w];
            sP[0] = r0 * Pp.x;          sQ[0] = r0 * Pm.x;
            sP[1] = sP[0] + r1 * Pp.y;  sQ[1] = sQ[0] + r1 * Pm.y;
            sP[2] = sP[1] + r2 * Pp.z;  sQ[2] = sQ[1] + r2 * Pm.z;
            sP[3] = sP[2] + r3 * Pp.w;  sQ[3] = sQ[2] + r3 * Pm.w;
            float iP = sP[3], iQ = sQ[3];
            #pragma unroll
            for (int o = 1; o < 32; o <<= 1) {
                float bP = __shfl_up_sync(FULL, iP, o);
                float bQ = __shfl_up_sync(FULL, iQ, o);
                if (lane >= o) { iP += bP; iQ += bQ; }
            }
            eP = iP - sP[3];  eQ = iQ - sQ[3];
            if (lane == 31) wt2[warp] = make_float2(iP, iQ);
        }
        __syncthreads();

        if (scanner) {
            int wl = warp - w0;
            float bP = eP, bQ = eQ;
            #pragma unroll 6
            for (int w = 0; w < wl; w++) { float2 v = wt2[w0 + w]; bP += v.x; bQ += v.y; }
            float* SP = role_e ? SPe : SPi;
            float* SQ = role_e ? SQe : SQi;
            ((float4*)SP)[seg] = make_float4(bP + sP[0], bP + sP[1], bP + sP[2], bP + sP[3]);
            ((float4*)SQ)[seg] = make_float4(bQ + sQ[0], bQ + sQ[1], bQ + sQ[2], bQ + sQ[3]);
        }
        if (t == 0 || t == 256) {
            float tot = 0.0f;
            #pragma unroll
            for (int w = 0; w < 7; w++) tot += wt2[w0 + w].y;
            if (t == 0) tot1 = tot; else tot3 = tot;
        }
        __syncthreads();

        float nv = 0.0f;
        if (t < NC) {
            float spe = poe ? SPe[poe - 1] : 0.0f;
            float sqe = poe ? SQe[poe - 1] : 0.0f;
            float spi = poi ? SPi[poi - 1] : 0.0f;
            float sqi = poi ? SQi[poi - 1] : 0.0f;
            float de  = Tm * spe + Tp * (tot1 - sqe);
            float di  = Tm * spi + Tp * (tot3 - sqi);
            float dot = (de - di) * inv;
            float conc = rc[t] * inv;
            if (it < WARM) {
                float dc = (d / (float)NTOT) * (ct * (1.0f / (float)NTOT) + dot);
                nv = fmaxf(conc + dc, 0.0f);
                rn[t] = nv;
            } else {
                g_base[t] = conc + (d / (float)NTOT) * dot;
            }
        }
        if (it == WARM) break;

        #pragma unroll
        for (int o = 16; o; o >>= 1) nv += __shfl_xor_sync(FULL, nv, o);
        if (lane == 0) wsum[warp] = nv;
        __syncthreads();
        if (warp == 0) {
            float v = wsum[lane];
            #pragma unroll
            for (int o = 16; o; o >>= 1) v += __shfl_xor_sync(FULL, v, o);
            if (lane == 0) s_sh = v;
        }
        __syncthreads();
        s = s_sh;
        float* tmp = rc; rc = rn; rn = tmp;
    }
}

// =================== k_gemm: 32-row tiles, 128 threads, 4 CTAs/SM ===========
#define SMA_H   0                  // 32 rows x 128B
#define SMA_L   4096
#define SMB_H   8192               // 64 rows x 128B
#define SMB_L   16384
#define SMBASE  24576              // 960 floats
#define SMRSUM  (SMBASE + 3840)    // 32 rows x 2 halves
#define SMTOT   (SMRSUM + 256)

__global__ void __launch_bounds__(128, 4)
k_gemm(const float* __restrict__ X, const float* __restrict__ delta,
       float* __restrict__ out) {
    extern __shared__ char sm[];
    const uint32_t sb = smem_u32(sm);
    float* sbase = (float*)(sm + SMBASE);
    float* srsum = (float*)(sm + SMRSUM);
    const int tid = threadIdx.x, wid = tid >> 5, lane = tid & 31;
    const int gr = lane >> 2, tg = lane & 3;
    const int r0 = blockIdx.x * 32;
    const int rg = wid >> 1;            // 0..1 -> rows rg*16..+16
    const int cg = wid & 1;             // col half: cg*32..+32
    const int m0 = rg * 16;

    for (int i = tid; i < NC; i += 128) sbase[i] = g_base[i];

    // A tile: 32x64 fp32 -> bf16 hi/lo, SW128 swizzled (1024 float2)
    for (int i = tid; i < 1024; i += 128) {
        int m = i >> 5, c2 = i & 31;
        float2 x = *(const float2*)(X + (size_t)(r0 + m) * 64 + 2 * c2);
        __nv_bfloat162 hp = __floats2bfloat162_rn(x.x, x.y);
        float2 hf = __bfloat1622float2(hp);
        __nv_bfloat162 lp = __floats2bfloat162_rn(x.x - hf.x, x.y - hf.y);
        uint32_t off = SW128((uint32_t)(m * 128 + c2 * 4));
        *(uint32_t*)(sm + SMA_H + off) = *(uint32_t*)&hp;
        *(uint32_t*)(sm + SMA_L + off) = *(uint32_t*)&lp;
    }
    __syncthreads();

    // chunk-invariant A fragments (per warp: its 16-row group, full K)
    uint32_t ah[4][4], al[4][4];
    {
        int arow = m0 + (lane & 7) + ((lane >> 3) & 1) * 8;
        int acol = (lane >> 4) & 1;
        #pragma unroll
        for (int ks = 0; ks < 4; ks++) {
            uint32_t off = SW128((uint32_t)(arow * 128 + (ks * 2 + acol) * 16));
            LDSM_X4(ah[ks][0], ah[ks][1], ah[ks][2], ah[ks][3], sb + SMA_H + off);
            LDSM_X4(al[ks][0], al[ks][1], al[ks][2], al[ks][3], sb + SMA_L + off);
        }
    }

    const float sc = delta[0] / (float)NTOT;
    float rsLo = 0.0f, rsHi = 0.0f;
    float2 vlo[4], vhi[4];

    const int brow_off = (lane & 7) + ((lane >> 4) & 1) * 8;
    const int bcol_off = (lane >> 3) & 1;

    for (int cc = 0; cc < 15; cc++) {
        // load B chunk (hi+lo): 1024 uint4 over 128 threads (sync LDG, proven)
        #pragma unroll
        for (int q = 0; q < 8; q++) {
            int f = q * 128 + tid;
            int isl = f >> 9;
            int r  = (f & 511) >> 3, ch = f & 7;
            const uint4* src = isl ? (const uint4*)g_Bl : (const uint4*)g_Bh;
            uint4 v = src[(size_t)(cc * 64 + r) * 8 + ch];
            uint32_t off = SW128((uint32_t)(r * 128 + ch * 16));
            *(uint4*)(sm + (isl ? SMB_L : SMB_H) + off) = v;
        }
        __syncthreads();

        float dacc[4][4];
        #pragma unroll
        for (int nt = 0; nt < 4; nt++)
            #pragma unroll
            for (int r = 0; r < 4; r++) dacc[nt][r] = 0.0f;

        #pragma unroll
        for (int ks = 0; ks < 4; ks++) {
            #pragma unroll
            for (int npl = 0; npl < 2; npl++) {
                int np = cg * 2 + npl;
                uint32_t boff = SW128((uint32_t)((np * 16 + brow_off) * 128 +
                                                 (ks * 2 + bcol_off) * 16));
                uint32_t b0, b1, b2, b3;
                LDSM_X4(b0, b1, b2, b3, sb + SMB_H + boff);
                MMA16816(dacc[npl * 2],     ah[ks], b0, b1);
                MMA16816(dacc[npl * 2 + 1], ah[ks], b2, b3);
                MMA16816(dacc[npl * 2],     al[ks], b0, b1);
                MMA16816(dacc[npl * 2 + 1], al[ks], b2, b3);
                LDSM_X4(b0, b1, b2, b3, sb + SMB_L + boff);
                MMA16816(dacc[npl * 2],     ah[ks], b0, b1);
                MMA16816(dacc[npl * 2 + 1], ah[ks], b2, b3);
            }
        }

        // epilogue: base + relu + row-sum partials (this warp's 32 cols)
        #pragma unroll
        for (int nt = 0; nt < 4; nt++) {
            float2 bb = *(const float2*)(sbase + cc * 64 + cg * 32 + nt * 8 + tg * 2);
            float v00 = fmaxf(bb.x + sc * dacc[nt][0], 0.0f);
            float v01 = fmaxf(bb.y + sc * dacc[nt][1], 0.0f);
            float v10 = fmaxf(bb.x + sc * dacc[nt][2], 0.0f);
            float v11 = fmaxf(bb.y + sc * dacc[nt][3], 0.0f);
            rsLo += v00 + v01;
            rsHi += v10 + v11;
            if (cc == 0) { vlo[nt] = make_float2(v00, v01);
                           vhi[nt] = make_float2(v10, v11); }
        }
        __syncthreads();
    }

    // row sums: quad-reduce, cross-warp combine of the 2 col halves
    rsLo += __shfl_xor_sync(FULL, rsLo, 1);
    rsLo += __shfl_xor_sync(FULL, rsLo, 2);
    rsHi += __shfl_xor_sync(FULL, rsHi, 1);
    rsHi += __shfl_xor_sync(FULL, rsHi, 2);
    if (tg == 0) {
        srsum[(m0 + gr) * 2 + cg]     = rsLo;
        srsum[(m0 + gr + 8) * 2 + cg] = rsHi;
    }
    __syncthreads();

    int rowLo = m0 + gr, rowHi = rowLo + 8;
    float tLo = srsum[rowLo * 2] + srsum[rowLo * 2 + 1];
    float tHi = srsum[rowHi * 2] + srsum[rowHi * 2 + 1];
    float invLo = (tLo > 0.0f) ? 1.0f / tLo : 1.0f;
    float invHi = (tHi > 0.0f) ? 1.0f / tHi : 1.0f;

    #pragma unroll
    for (int nt = 0; nt < 4; nt++) {
        int c = cg * 32 + nt * 8 + tg * 2;
        *(float2*)(out + (size_t)(r0 + rowLo) * 64 + c) =
            make_float2(vlo[nt].x * invLo, vlo[nt].y * invLo);
        *(float2*)(out + (size_t)(r0 + rowHi) * 64 + c) =
            make_float2(vhi[nt].x * invHi, vhi[nt].y * invHi);
    }
}

// ---------------- launch ----------------
extern "C" void kernel_launch(void* const* d_in, const int* in_sizes, int n_in,
                              void* d_out, int out_size) {
    const float* inputs      = (const float*)d_in[0];
    const float* identifiers = (const float*)d_in[1];
    const float* enhancers   = (const float*)d_in[2];
    const float* inhibitors  = (const float*)d_in[3];
    const float* beta        = (const float*)d_in[4];
    const float* delta       = (const float*)d_in[5];
    (void)in_sizes; (void)n_in; (void)out_size;

    cudaFuncSetAttribute(k_gemm, cudaFuncAttributeMaxDynamicSharedMemorySize, SMTOT);

    k_init<<<828, 256>>>(identifiers, enhancers, inhibitors, beta);
    k_warm<<<1, 1024>>>(delta);
    k_gemm<<<512, 128, SMTOT>>>(inputs, delta, (float*)d_out);
}

// round 14
// speedup vs baseline: 1.0947x; 1.0237x over previous
#include <cuda_runtime.h>
#include <cuda_bf16.h>
#include <math.h>
#include <stdint.h>

#define NTOT 1024
#define NI   64
#define NC   960
#define NR   896
#define WARM 25
#define FULL 0xffffffffu

// ---------------- device scratch ----------------
__device__ __align__(16) __nv_bfloat16 g_Bh[NC * 64];
__device__ __align__(16) __nv_bfloat16 g_Bl[NC * 64];
__device__ __align__(16) float g_Ep[NR], g_Em[NR], g_Ip[NR], g_Im[NR];
__device__ __align__(16) int   g_pidx_e[NR], g_pidx_i[NR];
__device__ __align__(16) int   g_pos_e[NC], g_pos_i[NC];
__device__ __align__(16) float g_Tp[NC], g_Tm[NC], g_ctop[NC];
__device__ __align__(16) float g_base[NC];

__device__ __forceinline__ uint32_t smem_u32(const void* p) {
    uint32_t a;
    asm("{ .reg .u64 t; cvta.to.shared.u64 t, %1; cvt.u32.u64 %0, t; }" : "=r"(a) : "l"(p));
    return a;
}
#define SW128(x) ((x) ^ (((x) >> 3) & 0x70))

#define LDSM_X4(r0, r1, r2, r3, a) \
    asm volatile("ldmatrix.sync.aligned.m8n8.x4.shared.b16 {%0,%1,%2,%3}, [%4];" \
        : "=r"(r0), "=r"(r1), "=r"(r2), "=r"(r3) : "r"(a))

#define MMA16816(d, a, b0, b1) \
    asm volatile("mma.sync.aligned.m16n8k16.row.col.f32.bf16.bf16.f32 " \
        "{%0,%1,%2,%3}, {%4,%5,%6,%7}, {%8,%9}, {%0,%1,%2,%3};" \
        : "+f"((d)[0]), "+f"((d)[1]), "+f"((d)[2]), "+f"((d)[3]) \
        : "r"((a)[0]), "r"((a)[1]), "r"((a)[2]), "r"((a)[3]), "r"(b0), "r"(b1))

// =================== k_init: ONE WAVE (148 x 1024) ===================
// blocks 0..59   : B bf16-split build (1 elem/thread)
// blocks 60..119 : tables (phase A: ranks/exps, phase B: pos/Tp/Tm/ctop)
// blocks 120..147: idle
__global__ void __launch_bounds__(1024, 1)
k_init(const float* __restrict__ ident, const float* __restrict__ enh,
       const float* __restrict__ inh,  const float* __restrict__ beta) {
    const int b = blockIdx.x, t = threadIdx.x;
    const int lane = t & 31, wid = t >> 5;
    const float bb = beta[0];

    if (b < 60) {                        // ---- B matrix build ----
        int idx = b * 1024 + t;          // 60*1024 = 61440 exactly
        int j = idx >> 6, k = idx & 63;
        float id = ident[NI + j];
        float v = expf(-bb * fabsf(enh[k] - id)) - expf(-bb * fabsf(inh[k] - id));
        __nv_bfloat16 h = __float2bfloat16(v);
        __nv_bfloat16 l = __float2bfloat16(v - __bfloat162float(h));
        g_Bh[idx] = h;
        g_Bl[idx] = l;
        return;
    }
    if (b >= 120) return;

    const int b2 = b - 60;               // 0..59
    // Phase A: ranks + permuted exp tables (warp per element; 1920 warp-tasks)
    {
        int W = b2 * 32 + wid;
        if (W < 2 * NR) {
            bool is_e = (W < NR);
            const float* arr = is_e ? enh : inh;
            int k = is_e ? W : (W - NR);
            float x = arr[128 + k];
            int cnt = 0;
            for (int k2 = lane; k2 < NR; k2 += 32) {
                float y = arr[128 + k2];
                cnt += (y < x) || (y == x && k2 < k);
            }
            #pragma unroll
            for (int o = 16; o; o >>= 1) cnt += __shfl_xor_sync(FULL, cnt, o);
            if (lane == 0) {
                if (is_e) { g_pidx_e[cnt] = k; g_Ep[cnt] = expf(bb * x); g_Em[cnt] = expf(-bb * x); }
                else      { g_pidx_i[cnt] = k; g_Ip[cnt] = expf(bb * x); g_Im[cnt] = expf(-bb * x); }
            }
        }
    }
    // Phase B: per-column tables; 16 columns per block, 2 warps per column
    {
        int j = b2 * 16 + (wid >> 1);
        int half = wid & 1;
        float tj = ident[NI + j];
        if (half == 0) {
            int cnt = 0;
            for (int k2 = lane; k2 < NR; k2 += 32) cnt += (enh[128 + k2] <= tj);
            #pragma unroll
            for (int o = 16; o; o >>= 1) cnt += __shfl_xor_sync(FULL, cnt, o);
            if (lane == 0) {
                g_pos_e[j] = cnt;
                g_Tp[j] = expf(bb * tj);
                g_Tm[j] = expf(-bb * tj);
            }
        } else {
            int cnt = 0;
            for (int k2 = lane; k2 < NR; k2 += 32) cnt += (inh[128 + k2] <= tj);
            float c = 0.0f;
            for (int k = lane; k < NI; k += 32)
                c += expf(-bb * fabsf(enh[k] - tj)) - expf(-bb * fabsf(inh[k] - tj));
            #pragma unroll
            for (int o = 16; o; o >>= 1) {
                cnt += __shfl_xor_sync(FULL, cnt, o);
                c   += __shfl_xor_sync(FULL, c, o);
            }
            if (lane == 0) { g_pos_i[j] = cnt; g_ctop[j] = c; }
        }
    }
}

// =================== k_warm: R7-exact ===================
__global__ void __launch_bounds__(1024, 1) k_warm(const float* __restrict__ delta) {
    __shared__ float rA[NC], rB[NC];
    __shared__ __align__(16) float SPe[NR], SQe[NR], SPi[NR], SQi[NR];
    __shared__ float2 wt2[16];
    __shared__ float wsum[32];
    __shared__ float tot1, tot3, s_sh;
    const int t = threadIdx.x, lane = t & 31, warp = t >> 5;

    const bool role_e = (t < 224);
    const bool role_i = (t >= 256 && t < 480);
    const bool scanner = role_e || role_i;
    const int seg = role_e ? t : (t - 256);
    const int w0  = role_e ? 0 : 8;

    int4 px = make_int4(0, 0, 0, 0);
    float4 Pp = make_float4(0, 0, 0, 0), Pm = Pp;
    if (role_e) {
        px = ((const int4*)g_pidx_e)[seg];
        Pp = ((const float4*)g_Ep)[seg];
        Pm = ((const float4*)g_Em)[seg];
    } else if (role_i) {
        px = ((const int4*)g_pidx_i)[seg];
        Pp = ((const float4*)g_Ip)[seg];
        Pm = ((const float4*)g_Im)[seg];
    }
    px.x += 64; px.y += 64; px.z += 64; px.w += 64;

    float Tp = 0, Tm = 0, ct = 0; int poe = 0, poi = 0;
    if (t < NC) { Tp = g_Tp[t]; Tm = g_Tm[t]; ct = g_ctop[t];
                  poe = g_pos_e[t]; poi = g_pos_i[t];
                  rA[t] = 1.0f / (float)NTOT; }
    float s = 1.0f;
    const float d = delta[0];
    __syncthreads();
    float *rc = rA, *rn = rB;

    for (int it = 0; it <= WARM; it++) {
        float inv = (s > 0.0f) ? 1.0f / s : 1.0f;

        float sP[4], sQ[4], eP = 0, eQ = 0;
        if (scanner) {
            float r0 = rc[px.x], r1 = rc[px.y], r2 = rc[px.z], r3 = rc[px.w];
            sP[0] = r0 * Pp.x;          sQ[0] = r0 * Pm.x;
            sP[1] = sP[0] + r1 * Pp.y;  sQ[1] = sQ[0] + r1 * Pm.y;
            sP[2] = sP[1] + r2 * Pp.z;  sQ[2] = sQ[1] + r2 * Pm.z;
            sP[3] = sP[2] + r3 * Pp.w;  sQ[3] = sQ[2] + r3 * Pm.w;
            float iP = sP[3], iQ = sQ[3];
            #pragma unroll
            for (int o = 1; o < 32; o <<= 1) {
                float bP = __shfl_up_sync(FULL, iP, o);
                float bQ = __shfl_up_sync(FULL, iQ, o);
                if (lane >= o) { iP += bP; iQ += bQ; }
            }
            eP = iP - sP[3];  eQ = iQ - sQ[3];
            if (lane == 31) wt2[warp] = make_float2(iP, iQ);
        }
        __syncthreads();

        if (scanner) {
            int wl = warp - w0;
            float bP = eP, bQ = eQ;
            #pragma unroll 6
            for (int w = 0; w < wl; w++) { float2 v = wt2[w0 + w]; bP += v.x; bQ += v.y; }
            float* SP = role_e ? SPe : SPi;
            float* SQ = role_e ? SQe : SQi;
            ((float4*)SP)[seg] = make_float4(bP + sP[0], bP + sP[1], bP + sP[2], bP + sP[3]);
            ((float4*)SQ)[seg] = make_float4(bQ + sQ[0], bQ + sQ[1], bQ + sQ[2], bQ + sQ[3]);
        }
        if (t == 0 || t == 256) {
            float tot = 0.0f;
            #pragma unroll
            for (int w = 0; w < 7; w++) tot += wt2[w0 + w].y;
            if (t == 0) tot1 = tot; else tot3 = tot;
        }
        __syncthreads();

        float nv = 0.0f;
        if (t < NC) {
            float spe = poe ? SPe[poe - 1] : 0.0f;
            float sqe = poe ? SQe[poe - 1] : 0.0f;
            float spi = poi ? SPi[poi - 1] : 0.0f;
            float sqi = poi ? SQi[poi - 1] : 0.0f;
            float de  = Tm * spe + Tp * (tot1 - sqe);
            float di  = Tm * spi + Tp * (tot3 - sqi);
            float dot = (de - di) * inv;
            float conc = rc[t] * inv;
            if (it < WARM) {
                float dc = (d / (float)NTOT) * (ct * (1.0f / (float)NTOT) + dot);
                nv = fmaxf(conc + dc, 0.0f);
                rn[t] = nv;
            } else {
                g_base[t] = conc + (d / (float)NTOT) * dot;
            }
        }
        if (it == WARM) break;

        #pragma unroll
        for (int o = 16; o; o >>= 1) nv += __shfl_xor_sync(FULL, nv, o);
        if (lane == 0) wsum[warp] = nv;
        __syncthreads();
        if (warp == 0) {
            float v = wsum[lane];
            #pragma unroll
            for (int o = 16; o; o >>= 1) v += __shfl_xor_sync(FULL, v, o);
            if (lane == 0) s_sh = v;
        }
        __syncthreads();
        s = s_sh;
        float* tmp = rc; rc = rn; rn = tmp;
    }
}

// =================== k_gemm: R11-exact (64-row tiles, 2 CTAs/SM) ============
#define SMA_H   0                  // 64 rows x 128B
#define SMA_L   8192
#define SMB_H   16384              // 64 rows x 128B
#define SMB_L   24576
#define SMBASE  32768              // 960 floats
#define SMRSUM  (SMBASE + 3840)    // 64 rows x 2 halves
#define SMTOT   (SMRSUM + 512)

__global__ void __launch_bounds__(256, 2)
k_gemm(const float* __restrict__ X, const float* __restrict__ delta,
       float* __restrict__ out) {
    extern __shared__ char sm[];
    const uint32_t sb = smem_u32(sm);
    float* sbase = (float*)(sm + SMBASE);
    float* srsum = (float*)(sm + SMRSUM);
    const int tid = threadIdx.x, wid = tid >> 5, lane = tid & 31;
    const int gr = lane >> 2, tg = lane & 3;
    const int r0 = blockIdx.x * 64;
    const int rg = wid >> 1;
    const int cg = wid & 1;
    const int m0 = rg * 16;

    for (int i = tid; i < NC; i += 256) sbase[i] = g_base[i];

    // A tile: 64x64 fp32 -> bf16 hi/lo, SW128 swizzled
    for (int i = tid; i < 2048; i += 256) {
        int m = i >> 5, c2 = i & 31;
        float2 x = *(const float2*)(X + (size_t)(r0 + m) * 64 + 2 * c2);
        __nv_bfloat162 hp = __floats2bfloat162_rn(x.x, x.y);
        float2 hf = __bfloat1622float2(hp);
        __nv_bfloat162 lp = __floats2bfloat162_rn(x.x - hf.x, x.y - hf.y);
        uint32_t off = SW128((uint32_t)(m * 128 + c2 * 4));
        *(uint32_t*)(sm + SMA_H + off) = *(uint32_t*)&hp;
        *(uint32_t*)(sm + SMA_L + off) = *(uint32_t*)&lp;
    }
    __syncthreads();

    uint32_t ah[4][4], al[4][4];
    {
        int arow = m0 + (lane & 7) + ((lane >> 3) & 1) * 8;
        int acol = (lane >> 4) & 1;
        #pragma unroll
        for (int ks = 0; ks < 4; ks++) {
            uint32_t off = SW128((uint32_t)(arow * 128 + (ks * 2 + acol) * 16));
            LDSM_X4(ah[ks][0], ah[ks][1], ah[ks][2], ah[ks][3], sb + SMA_H + off);
            LDSM_X4(al[ks][0], al[ks][1], al[ks][2], al[ks][3], sb + SMA_L + off);
        }
    }

    const float sc = delta[0] / (float)NTOT;
    float rsLo = 0.0f, rsHi = 0.0f;
    float2 vlo[4], vhi[4];

    const int brow_off = (lane & 7) + ((lane >> 4) & 1) * 8;
    const int bcol_off = (lane >> 3) & 1;

    for (int cc = 0; cc < 15; cc++) {
        #pragma unroll
        for (int q = 0; q < 4; q++) {
            int f = q * 256 + tid;
            int isl = f >> 9;
            int r  = (f & 511) >> 3, ch = f & 7;
            const uint4* src = isl ? (const uint4*)g_Bl : (const uint4*)g_Bh;
            uint4 v = src[(size_t)(cc * 64 + r) * 8 + ch];
            uint32_t off = SW128((uint32_t)(r * 128 + ch * 16));
            *(uint4*)(sm + (isl ? SMB_L : SMB_H) + off) = v;
        }
        __syncthreads();

        float dacc[4][4];
        #pragma unroll
        for (int nt = 0; nt < 4; nt++)
            #pragma unroll
            for (int r = 0; r < 4; r++) dacc[nt][r] = 0.0f;

        #pragma unroll
        for (int ks = 0; ks < 4; ks++) {
            #pragma unroll
            for (int npl = 0; npl < 2; npl++) {
                int np = cg * 2 + npl;
                uint32_t boff = SW128((uint32_t)((np * 16 + brow_off) * 128 +
                                                 (ks * 2 + bcol_off) * 16));
                uint32_t b0, b1, b2, b3;
                LDSM_X4(b0, b1, b2, b3, sb + SMB_H + boff);
                MMA16816(dacc[npl * 2],     ah[ks], b0, b1);
                MMA16816(dacc[npl * 2 + 1], ah[ks], b2, b3);
                MMA16816(dacc[npl * 2],     al[ks], b0, b1);
                MMA16816(dacc[npl * 2 + 1], al[ks], b2, b3);
                LDSM_X4(b0, b1, b2, b3, sb + SMB_L + boff);
                MMA16816(dacc[npl * 2],     ah[ks], b0, b1);
                MMA16816(dacc[npl * 2 + 1], ah[ks], b2, b3);
            }
        }

        #pragma unroll
        for (int nt = 0; nt < 4; nt++) {
            float2 bb = *(const float2*)(sbase + cc * 64 + cg * 32 + nt * 8 + tg * 2);
            float v00 = fmaxf(bb.x + sc * dacc[nt][0], 0.0f);
            float v01 = fmaxf(bb.y + sc * dacc[nt][1], 0.0f);
            float v10 = fmaxf(bb.x + sc * dacc[nt][2], 0.0f);
            float v11 = fmaxf(bb.y + sc * dacc[nt][3], 0.0f);
            rsLo += v00 + v01;
            rsHi += v10 + v11;
            if (cc == 0) { vlo[nt] = make_float2(v00, v01);
                           vhi[nt] = make_float2(v10, v11); }
        }
        __syncthreads();
    }

    rsLo += __shfl_xor_sync(FULL, rsLo, 1);
    rsLo += __shfl_xor_sync(FULL, rsLo, 2);
    rsHi += __shfl_xor_sync(FULL, rsHi, 1);
    rsHi += __shfl_xor_sync(FULL, rsHi, 2);
    if (tg == 0) {
        srsum[(m0 + gr) * 2 + cg]     = rsLo;
        srsum[(m0 + gr + 8) * 2 + cg] = rsHi;
    }
    __syncthreads();

    int rowLo = m0 + gr, rowHi = rowLo + 8;
    float tLo = srsum[rowLo * 2] + srsum[rowLo * 2 + 1];
    float tHi = srsum[rowHi * 2] + srsum[rowHi * 2 + 1];
    float invLo = (tLo > 0.0f) ? 1.0f / tLo : 1.0f;
    float invHi = (tHi > 0.0f) ? 1.0f / tHi : 1.0f;

    #pragma unroll
    for (int nt = 0; nt < 4; nt++) {
        int c = cg * 32 + nt * 8 + tg * 2;
        *(float2*)(out + (size_t)(r0 + rowLo) * 64 + c) =
            make_float2(vlo[nt].x * invLo, vlo[nt].y * invLo);
        *(float2*)(out + (size_t)(r0 + rowHi) * 64 + c) =
            make_float2(vhi[nt].x * invHi, vhi[nt].y * invHi);
    }
}

// ---------------- launch ----------------
extern "C" void kernel_launch(void* const* d_in, const int* in_sizes, int n_in,
                              void* d_out, int out_size) {
    const float* inputs      = (const float*)d_in[0];
    const float* identifiers = (const float*)d_in[1];
    const float* enhancers   = (const float*)d_in[2];
    const float* inhibitors  = (const float*)d_in[3];
    const float* beta        = (const float*)d_in[4];
    const float* delta       = (const float*)d_in[5];
    (void)in_sizes; (void)n_in; (void)out_size;

    cudaFuncSetAttribute(k_gemm, cudaFuncAttributeMaxDynamicSharedMemorySize, SMTOT);

    k_init<<<148, 1024>>>(identifiers, enhancers, inhibitors, beta);
    k_warm<<<1, 1024>>>(delta);
    k_gemm<<<256, 256, SMTOT>>>(inputs, delta, (float*)d_out);
}

// round 15
// speedup vs baseline: 1.1949x; 1.0916x over previous
#include <cuda_runtime.h>
#include <cuda_bf16.h>
#include <math.h>
#include <stdint.h>

#define NTOT 1024
#define NI   64
#define NC   960
#define NR   896
#define WARM 25
#define FULL 0xffffffffu

// ---------------- device scratch ----------------
__device__ __align__(16) __nv_bfloat16 g_Bh[NC * 64];
__device__ __align__(16) __nv_bfloat16 g_Bl[NC * 64];
__device__ __align__(16) float g_Ep[NR], g_Em[NR], g_Ip[NR], g_Im[NR];
__device__ __align__(16) int   g_pidx_e[NR], g_pidx_i[NR];
__device__ __align__(16) int   g_pos_e[NC], g_pos_i[NC];
__device__ __align__(16) float g_Tp[NC], g_Tm[NC], g_ctop[NC];
__device__ __align__(16) float g_base[NC];

__device__ __forceinline__ uint32_t smem_u32(const void* p) {
    uint32_t a;
    asm("{ .reg .u64 t; cvta.to.shared.u64 t, %1; cvt.u32.u64 %0, t; }" : "=r"(a) : "l"(p));
    return a;
}
#define SW128(x) ((x) ^ (((x) >> 3) & 0x70))

#define LDSM_X4(r0, r1, r2, r3, a) \
    asm volatile("ldmatrix.sync.aligned.m8n8.x4.shared.b16 {%0,%1,%2,%3}, [%4];" \
        : "=r"(r0), "=r"(r1), "=r"(r2), "=r"(r3) : "r"(a))

#define MMA16816(d, a, b0, b1) \
    asm volatile("mma.sync.aligned.m16n8k16.row.col.f32.bf16.bf16.f32 " \
        "{%0,%1,%2,%3}, {%4,%5,%6,%7}, {%8,%9}, {%0,%1,%2,%3};" \
        : "+f"((d)[0]), "+f"((d)[1]), "+f"((d)[2]), "+f"((d)[3]) \
        : "r"((a)[0]), "r"((a)[1]), "r"((a)[2]), "r"((a)[3]), "r"(b0), "r"(b1))

// =================== k_init: R7/R11-exact (828 x 256) ===================
__global__ void k_init(const float* __restrict__ ident, const float* __restrict__ enh,
                       const float* __restrict__ inh,  const float* __restrict__ beta) {
    const int b = blockIdx.x, t = threadIdx.x;
    const int wid = t >> 5, lane = t & 31;
    const float bb = beta[0];

    if (b < 240) {
        int idx = b * 256 + t;
        int j = idx >> 6, k = idx & 63;
        float id = ident[NI + j];
        float v = expf(-bb * fabsf(enh[k] - id)) - expf(-bb * fabsf(inh[k] - id));
        __nv_bfloat16 h = __float2bfloat16(v);
        __nv_bfloat16 l = __float2bfloat16(v - __bfloat162float(h));
        g_Bh[idx] = h;
        g_Bl[idx] = l;
    } else if (b < 464) {
        bool is_e = (b < 352);
        const float* arr = is_e ? enh : inh;
        int k = ((b - (is_e ? 240 : 352)) * 8 + wid);
        float x = arr[128 + k];
        int cnt = 0;
        for (int k2 = lane; k2 < NR; k2 += 32) {
            float y = arr[128 + k2];
            cnt += (y < x) || (y == x && k2 < k);
        }
        #pragma unroll
        for (int o = 16; o; o >>= 1) cnt += __shfl_xor_sync(FULL, cnt, o);
        if (lane == 0) {
            if (is_e) { g_pidx_e[cnt] = k; g_Ep[cnt] = expf(bb * x); g_Em[cnt] = expf(-bb * x); }
            else      { g_pidx_i[cnt] = k; g_Ip[cnt] = expf(bb * x); g_Im[cnt] = expf(-bb * x); }
        }
    } else if (b < 704) {
        bool is_e = (b < 584);
        const float* arr = is_e ? enh : inh;
        int j = ((b - (is_e ? 464 : 584)) * 8 + wid);
        float tj = ident[NI + j];
        int cnt = 0;
        for (int k2 = lane; k2 < NR; k2 += 32) cnt += (arr[128 + k2] <= tj);
        #pragma unroll
        for (int o = 16; o; o >>= 1) cnt += __shfl_xor_sync(FULL, cnt, o);
        if (lane == 0) { if (is_e) g_pos_e[j] = cnt; else g_pos_i[j] = cnt; }
    } else if (b < 824) {
        int j = (b - 704) * 8 + wid;
        float tj = ident[NI + j];
        float c = 0.0f;
        for (int k = lane; k < NI; k += 32)
            c += expf(-bb * fabsf(enh[k] - tj)) - expf(-bb * fabsf(inh[k] - tj));
        #pragma unroll
        for (int o = 16; o; o >>= 1) c += __shfl_xor_sync(FULL, c, o);
        if (lane == 0) g_ctop[j] = c;
    } else {
        int j = (b - 824) * 256 + t;
        if (j < NC) {
            float tj = ident[NI + j];
            g_Tp[j] = expf(bb * tj);
            g_Tm[j] = expf(-bb * tj);
        }
    }
}

// =================== k_warm: 512 threads, scanners unchanged ================
// scanners: warps 0-6 (e, threads 0..223), warps 8-14 (i, threads 256..479)
// consumers: thread t handles columns t and t+512 (t+512 < 960 iff t < 448)
__global__ void __launch_bounds__(512, 1) k_warm(const float* __restrict__ delta) {
    __shared__ float rA[NC], rB[NC];
    __shared__ __align__(16) float SPe[NR], SQe[NR], SPi[NR], SQi[NR];
    __shared__ float2 wt2[16];
    __shared__ float wsum[16];
    __shared__ float tot1, tot3, s_sh;
    const int t = threadIdx.x, lane = t & 31, warp = t >> 5;

    const bool role_e = (t < 224);
    const bool role_i = (t >= 256 && t < 480);
    const bool scanner = role_e || role_i;
    const int seg = role_e ? t : (t - 256);
    const int w0  = role_e ? 0 : 8;

    int4 px = make_int4(0, 0, 0, 0);
    float4 Pp = make_float4(0, 0, 0, 0), Pm = Pp;
    if (role_e) {
        px = ((const int4*)g_pidx_e)[seg];
        Pp = ((const float4*)g_Ep)[seg];
        Pm = ((const float4*)g_Em)[seg];
    } else if (role_i) {
        px = ((const int4*)g_pidx_i)[seg];
        Pp = ((const float4*)g_Ip)[seg];
        Pm = ((const float4*)g_Im)[seg];
    }
    px.x += 64; px.y += 64; px.z += 64; px.w += 64;

    // consumer state for two columns: j0 = t, j1 = t + 512
    const int j1 = t + 512;
    const bool c1v = (j1 < NC);
    float Tp0 = g_Tp[t], Tm0 = g_Tm[t], ct0 = g_ctop[t];
    int poe0 = g_pos_e[t], poi0 = g_pos_i[t];
    float Tp1 = 0, Tm1 = 0, ct1 = 0; int poe1 = 0, poi1 = 0;
    if (c1v) { Tp1 = g_Tp[j1]; Tm1 = g_Tm[j1]; ct1 = g_ctop[j1];
               poe1 = g_pos_e[j1]; poi1 = g_pos_i[j1]; }
    rA[t] = 1.0f / (float)NTOT;
    if (c1v) rA[j1] = 1.0f / (float)NTOT;

    float s = 1.0f;
    const float d = delta[0];
    __syncthreads();
    float *rc = rA, *rn = rB;

    for (int it = 0; it <= WARM; it++) {
        float inv = (s > 0.0f) ? 1.0f / s : 1.0f;

        float sP[4], sQ[4], eP = 0, eQ = 0;
        if (scanner) {
            float r0 = rc[px.x], r1 = rc[px.y], r2 = rc[px.z], r3 = rc[px.w];
            sP[0] = r0 * Pp.x;          sQ[0] = r0 * Pm.x;
            sP[1] = sP[0] + r1 * Pp.y;  sQ[1] = sQ[0] + r1 * Pm.y;
            sP[2] = sP[1] + r2 * Pp.z;  sQ[2] = sQ[1] + r2 * Pm.z;
            sP[3] = sP[2] + r3 * Pp.w;  sQ[3] = sQ[2] + r3 * Pm.w;
            float iP = sP[3], iQ = sQ[3];
            #pragma unroll
            for (int o = 1; o < 32; o <<= 1) {
                float bP = __shfl_up_sync(FULL, iP, o);
                float bQ = __shfl_up_sync(FULL, iQ, o);
                if (lane >= o) { iP += bP; iQ += bQ; }
            }
            eP = iP - sP[3];  eQ = iQ - sQ[3];
            if (lane == 31) wt2[warp] = make_float2(iP, iQ);
        }
        __syncthreads();                                   // (1)

        if (scanner) {
            int wl = warp - w0;
            float bP = eP, bQ = eQ;
            #pragma unroll 6
            for (int w = 0; w < wl; w++) { float2 v = wt2[w0 + w]; bP += v.x; bQ += v.y; }
            float* SP = role_e ? SPe : SPi;
            float* SQ = role_e ? SQe : SQi;
            ((float4*)SP)[seg] = make_float4(bP + sP[0], bP + sP[1], bP + sP[2], bP + sP[3]);
            ((float4*)SQ)[seg] = make_float4(bQ + sQ[0], bQ + sQ[1], bQ + sQ[2], bQ + sQ[3]);
        }
        if (t == 0 || t == 256) {
            float tot = 0.0f;
            #pragma unroll
            for (int w = 0; w < 7; w++) tot += wt2[w0 + w].y;
            if (t == 0) tot1 = tot; else tot3 = tot;
        }
        __syncthreads();                                   // (2)

        float nv = 0.0f;
        {
            // column j0 = t
            float spe = poe0 ? SPe[poe0 - 1] : 0.0f;
            float sqe = poe0 ? SQe[poe0 - 1] : 0.0f;
            float spi = poi0 ? SPi[poi0 - 1] : 0.0f;
            float sqi = poi0 ? SQi[poi0 - 1] : 0.0f;
            float de  = Tm0 * spe + Tp0 * (tot1 - sqe);
            float di  = Tm0 * spi + Tp0 * (tot3 - sqi);
            float dot = (de - di) * inv;
            float conc = rc[t] * inv;
            if (it < WARM) {
                float dc = (d / (float)NTOT) * (ct0 * (1.0f / (float)NTOT) + dot);
                float v = fmaxf(conc + dc, 0.0f);
                rn[t] = v;
                nv += v;
            } else {
                g_base[t] = conc + (d / (float)NTOT) * dot;
            }
        }
        if (c1v) {
            // column j1 = t + 512
            float spe = poe1 ? SPe[poe1 - 1] : 0.0f;
            float sqe = poe1 ? SQe[poe1 - 1] : 0.0f;
            float spi = poi1 ? SPi[poi1 - 1] : 0.0f;
            float sqi = poi1 ? SQi[poi1 - 1] : 0.0f;
            float de  = Tm1 * spe + Tp1 * (tot1 - sqe);
            float di  = Tm1 * spi + Tp1 * (tot3 - sqi);
            float dot = (de - di) * inv;
            float conc = rc[j1] * inv;
            if (it < WARM) {
                float dc = (d / (float)NTOT) * (ct1 * (1.0f / (float)NTOT) + dot);
                float v = fmaxf(conc + dc, 0.0f);
                rn[j1] = v;
                nv += v;
            } else {
                g_base[j1] = conc + (d / (float)NTOT) * dot;
            }
        }
        if (it == WARM) break;

        #pragma unroll
        for (int o = 16; o; o >>= 1) nv += __shfl_xor_sync(FULL, nv, o);
        if (lane == 0) wsum[warp] = nv;
        __syncthreads();                                   // (3)
        if (warp == 0) {
            float v = (lane < 16) ? wsum[lane] : 0.0f;
            #pragma unroll
            for (int o = 8; o; o >>= 1) v += __shfl_xor_sync(FULL, v, o);
            if (lane == 0) s_sh = v;
        }
        __syncthreads();                                   // (4)
        s = s_sh;
        float* tmp = rc; rc = rn; rn = tmp;
    }
}

// =================== k_gemm: R11-exact (64-row tiles, 2 CTAs/SM) ============
#define SMA_H   0                  // 64 rows x 128B
#define SMA_L   8192
#define SMB_H   16384              // 64 rows x 128B
#define SMB_L   24576
#define SMBASE  32768              // 960 floats
#define SMRSUM  (SMBASE + 3840)    // 64 rows x 2 halves
#define SMTOT   (SMRSUM + 512)

__global__ void __launch_bounds__(256, 2)
k_gemm(const float* __restrict__ X, const float* __restrict__ delta,
       float* __restrict__ out) {
    extern __shared__ char sm[];
    const uint32_t sb = smem_u32(sm);
    float* sbase = (float*)(sm + SMBASE);
    float* srsum = (float*)(sm + SMRSUM);
    const int tid = threadIdx.x, wid = tid >> 5, lane = tid & 31;
    const int gr = lane >> 2, tg = lane & 3;
    const int r0 = blockIdx.x * 64;
    const int rg = wid >> 1;
    const int cg = wid & 1;
    const int m0 = rg * 16;

    for (int i = tid; i < NC; i += 256) sbase[i] = g_base[i];

    for (int i = tid; i < 2048; i += 256) {
        int m = i >> 5, c2 = i & 31;
        float2 x = *(const float2*)(X + (size_t)(r0 + m) * 64 + 2 * c2);
        __nv_bfloat162 hp = __floats2bfloat162_rn(x.x, x.y);
        float2 hf = __bfloat1622float2(hp);
        __nv_bfloat162 lp = __floats2bfloat162_rn(x.x - hf.x, x.y - hf.y);
        uint32_t off = SW128((uint32_t)(m * 128 + c2 * 4));
        *(uint32_t*)(sm + SMA_H + off) = *(uint32_t*)&hp;
        *(uint32_t*)(sm + SMA_L + off) = *(uint32_t*)&lp;
    }
    __syncthreads();

    uint32_t ah[4][4], al[4][4];
    {
        int arow = m0 + (lane & 7) + ((lane >> 3) & 1) * 8;
        int acol = (lane >> 4) & 1;
        #pragma unroll
        for (int ks = 0; ks < 4; ks++) {
            uint32_t off = SW128((uint32_t)(arow * 128 + (ks * 2 + acol) * 16));
            LDSM_X4(ah[ks][0], ah[ks][1], ah[ks][2], ah[ks][3], sb + SMA_H + off);
            LDSM_X4(al[ks][0], al[ks][1], al[ks][2], al[ks][3], sb + SMA_L + off);
        }
    }

    const float sc = delta[0] / (float)NTOT;
    float rsLo = 0.0f, rsHi = 0.0f;
    float2 vlo[4], vhi[4];

    const int brow_off = (lane & 7) + ((lane >> 4) & 1) * 8;
    const int bcol_off = (lane >> 3) & 1;

    for (int cc = 0; cc < 15; cc++) {
        #pragma unroll
        for (int q = 0; q < 4; q++) {
            int f = q * 256 + tid;
            int isl = f >> 9;
            int r  = (f & 511) >> 3, ch = f & 7;
            const uint4* src = isl ? (const uint4*)g_Bl : (const uint4*)g_Bh;
            uint4 v = src[(size_t)(cc * 64 + r) * 8 + ch];
            uint32_t off = SW128((uint32_t)(r * 128 + ch * 16));
            *(uint4*)(sm + (isl ? SMB_L : SMB_H) + off) = v;
        }
        __syncthreads();

        float dacc[4][4];
        #pragma unroll
        for (int nt = 0; nt < 4; nt++)
            #pragma unroll
            for (int r = 0; r < 4; r++) dacc[nt][r] = 0.0f;

        #pragma unroll
        for (int ks = 0; ks < 4; ks++) {
            #pragma unroll
            for (int npl = 0; npl < 2; npl++) {
                int np = cg * 2 + npl;
                uint32_t boff = SW128((uint32_t)((np * 16 + brow_off) * 128 +
                                                 (ks * 2 + bcol_off) * 16));
                uint32_t b0, b1, b2, b3;
                LDSM_X4(b0, b1, b2, b3, sb + SMB_H + boff);
                MMA16816(dacc[npl * 2],     ah[ks], b0, b1);
                MMA16816(dacc[npl * 2 + 1], ah[ks], b2, b3);
                MMA16816(dacc[npl * 2],     al[ks], b0, b1);
                MMA16816(dacc[npl * 2 + 1], al[ks], b2, b3);
                LDSM_X4(b0, b1, b2, b3, sb + SMB_L + boff);
                MMA16816(dacc[npl * 2],     ah[ks], b0, b1);
                MMA16816(dacc[npl * 2 + 1], ah[ks], b2, b3);
            }
        }

        #pragma unroll
        for (int nt = 0; nt < 4; nt++) {
            float2 bb = *(const float2*)(sbase + cc * 64 + cg * 32 + nt * 8 + tg * 2);
            float v00 = fmaxf(bb.x + sc * dacc[nt][0], 0.0f);
            float v01 = fmaxf(bb.y + sc * dacc[nt][1], 0.0f);
            float v10 = fmaxf(bb.x + sc * dacc[nt][2], 0.0f);
            float v11 = fmaxf(bb.y + sc * dacc[nt][3], 0.0f);
            rsLo += v00 + v01;
            rsHi += v10 + v11;
            if (cc == 0) { vlo[nt] = make_float2(v00, v01);
                           vhi[nt] = make_float2(v10, v11); }
        }
        __syncthreads();
    }

    rsLo += __shfl_xor_sync(FULL, rsLo, 1);
    rsLo += __shfl_xor_sync(FULL, rsLo, 2);
    rsHi += __shfl_xor_sync(FULL, rsHi, 1);
    rsHi += __shfl_xor_sync(FULL, rsHi, 2);
    if (tg == 0) {
        srsum[(m0 + gr) * 2 + cg]     = rsLo;
        srsum[(m0 + gr + 8) * 2 + cg] = rsHi;
    }
    __syncthreads();

    int rowLo = m0 + gr, rowHi = rowLo + 8;
    float tLo = srsum[rowLo * 2] + srsum[rowLo * 2 + 1];
    float tHi = srsum[rowHi * 2] + srsum[rowHi * 2 + 1];
    float invLo = (tLo > 0.0f) ? 1.0f / tLo : 1.0f;
    float invHi = (tHi > 0.0f) ? 1.0f / tHi : 1.0f;

    #pragma unroll
    for (int nt = 0; nt < 4; nt++) {
        int c = cg * 32 + nt * 8 + tg * 2;
        *(float2*)(out + (size_t)(r0 + rowLo) * 64 + c) =
            make_float2(vlo[nt].x * invLo, vlo[nt].y * invLo);
        *(float2*)(out + (size_t)(r0 + rowHi) * 64 + c) =
            make_float2(vhi[nt].x * invHi, vhi[nt].y * invHi);
    }
}

// ---------------- launch ----------------
extern "C" void kernel_launch(void* const* d_in, const int* in_sizes, int n_in,
                              void* d_out, int out_size) {
    const float* inputs      = (const float*)d_in[0];
    const float* identifiers = (const float*)d_in[1];
    const float* enhancers   = (const float*)d_in[2];
    const float* inhibitors  = (const float*)d_in[3];
    const float* beta        = (const float*)d_in[4];
    const float* delta       = (const float*)d_in[5];
    (void)in_sizes; (void)n_in; (void)out_size;

    cudaFuncSetAttribute(k_gemm, cudaFuncAttributeMaxDynamicSharedMemorySize, SMTOT);

    k_init<<<828, 256>>>(identifiers, enhancers, inhibitors, beta);
    k_warm<<<1, 512>>>(delta);
    k_gemm<<<256, 256, SMTOT>>>(inputs, delta, (float*)d_out);
}

// round 16
// speedup vs baseline: 1.2106x; 1.0131x over previous
#include <cuda_runtime.h>
#include <cuda_bf16.h>
#include <math.h>
#include <stdint.h>

#define NTOT 1024
#define NI   64
#define NC   960
#define NR   896
#define WARM 25
#define FULL 0xffffffffu

// ---------------- device scratch ----------------
__device__ __align__(16) __nv_bfloat16 g_Bh[NC * 64];
__device__ __align__(16) __nv_bfloat16 g_Bl[NC * 64];
__device__ __align__(16) float g_Ep[NR], g_Em[NR], g_Ip[NR], g_Im[NR];
__device__ __align__(16) int   g_pidx_e[NR], g_pidx_i[NR];
__device__ __align__(16) int   g_pos_e[NC], g_pos_i[NC];
__device__ __align__(16) float g_Tp[NC], g_Tm[NC], g_ctop[NC];
__device__ __align__(16) float g_base[NC];

__device__ __forceinline__ uint32_t smem_u32(const void* p) {
    uint32_t a;
    asm("{ .reg .u64 t; cvta.to.shared.u64 t, %1; cvt.u32.u64 %0, t; }" : "=r"(a) : "l"(p));
    return a;
}
#define SW128(x) ((x) ^ (((x) >> 3) & 0x70))

#define LDSM_X4(r0, r1, r2, r3, a) \
    asm volatile("ldmatrix.sync.aligned.m8n8.x4.shared.b16 {%0,%1,%2,%3}, [%4];" \
        : "=r"(r0), "=r"(r1), "=r"(r2), "=r"(r3) : "r"(a))

#define MMA16816(d, a, b0, b1) \
    asm volatile("mma.sync.aligned.m16n8k16.row.col.f32.bf16.bf16.f32 " \
        "{%0,%1,%2,%3}, {%4,%5,%6,%7}, {%8,%9}, {%0,%1,%2,%3};" \
        : "+f"((d)[0]), "+f"((d)[1]), "+f"((d)[2]), "+f"((d)[3]) \
        : "r"((a)[0]), "r"((a)[1]), "r"((a)[2]), "r"((a)[3]), "r"(b0), "r"(b1))

// =================== k_init: R7/R11-exact (828 x 256) ===================
__global__ void k_init(const float* __restrict__ ident, const float* __restrict__ enh,
                       const float* __restrict__ inh,  const float* __restrict__ beta) {
    const int b = blockIdx.x, t = threadIdx.x;
    const int wid = t >> 5, lane = t & 31;
    const float bb = beta[0];

    if (b < 240) {
        int idx = b * 256 + t;
        int j = idx >> 6, k = idx & 63;
        float id = ident[NI + j];
        float v = expf(-bb * fabsf(enh[k] - id)) - expf(-bb * fabsf(inh[k] - id));
        __nv_bfloat16 h = __float2bfloat16(v);
        __nv_bfloat16 l = __float2bfloat16(v - __bfloat162float(h));
        g_Bh[idx] = h;
        g_Bl[idx] = l;
    } else if (b < 464) {
        bool is_e = (b < 352);
        const float* arr = is_e ? enh : inh;
        int k = ((b - (is_e ? 240 : 352)) * 8 + wid);
        float x = arr[128 + k];
        int cnt = 0;
        for (int k2 = lane; k2 < NR; k2 += 32) {
            float y = arr[128 + k2];
            cnt += (y < x) || (y == x && k2 < k);
        }
        #pragma unroll
        for (int o = 16; o; o >>= 1) cnt += __shfl_xor_sync(FULL, cnt, o);
        if (lane == 0) {
            if (is_e) { g_pidx_e[cnt] = k; g_Ep[cnt] = expf(bb * x); g_Em[cnt] = expf(-bb * x); }
            else      { g_pidx_i[cnt] = k; g_Ip[cnt] = expf(bb * x); g_Im[cnt] = expf(-bb * x); }
        }
    } else if (b < 704) {
        bool is_e = (b < 584);
        const float* arr = is_e ? enh : inh;
        int j = ((b - (is_e ? 464 : 584)) * 8 + wid);
        float tj = ident[NI + j];
        int cnt = 0;
        for (int k2 = lane; k2 < NR; k2 += 32) cnt += (arr[128 + k2] <= tj);
        #pragma unroll
        for (int o = 16; o; o >>= 1) cnt += __shfl_xor_sync(FULL, cnt, o);
        if (lane == 0) { if (is_e) g_pos_e[j] = cnt; else g_pos_i[j] = cnt; }
    } else if (b < 824) {
        int j = (b - 704) * 8 + wid;
        float tj = ident[NI + j];
        float c = 0.0f;
        for (int k = lane; k < NI; k += 32)
            c += expf(-bb * fabsf(enh[k] - tj)) - expf(-bb * fabsf(inh[k] - tj));
        #pragma unroll
        for (int o = 16; o; o >>= 1) c += __shfl_xor_sync(FULL, c, o);
        if (lane == 0) g_ctop[j] = c;
    } else {
        int j = (b - 824) * 256 + t;
        if (j < NC) {
            float tj = ident[NI + j];
            g_Tp[j] = expf(bb * tj);
            g_Tm[j] = expf(-bb * tj);
        }
    }
}

// =================== k_warm: 256 threads, merged e/i scanners ===============
// scanners: t < 224 (warps 0-6), each owns 4 e-elements AND 4 i-elements.
// consumers: thread t handles columns t, t+256, t+512, t+768 (< 960).
__global__ void __launch_bounds__(256, 1) k_warm(const float* __restrict__ delta) {
    __shared__ float rA[NC], rB[NC];
    __shared__ __align__(16) float SPe[NR], SQe[NR], SPi[NR], SQi[NR];
    __shared__ float4 wt4[8];
    __shared__ float wsum[8];
    __shared__ float tot1, tot3, s_sh;
    const int t = threadIdx.x, lane = t & 31, warp = t >> 5;

    const bool scanner = (t < 224);
    const int seg = t;

    int4 pe = make_int4(0, 0, 0, 0), pi = pe;
    float4 Ep = make_float4(0, 0, 0, 0), Em = Ep, Ip = Ep, Im = Ep;
    if (scanner) {
        pe = ((const int4*)g_pidx_e)[seg];
        pi = ((const int4*)g_pidx_i)[seg];
        Ep = ((const float4*)g_Ep)[seg];
        Em = ((const float4*)g_Em)[seg];
        Ip = ((const float4*)g_Ip)[seg];
        Im = ((const float4*)g_Im)[seg];
        pe.x += 64; pe.y += 64; pe.z += 64; pe.w += 64;
        pi.x += 64; pi.y += 64; pi.z += 64; pi.w += 64;
    }

    // consumer state: 4 columns j = t + 256*q
    float Tpc[4], Tmc[4], ctc[4];
    int poec[4], poic[4];
    int ncols = 0;
    #pragma unroll
    for (int q = 0; q < 4; q++) {
        int j = t + 256 * q;
        if (j < NC) {
            Tpc[q] = g_Tp[j]; Tmc[q] = g_Tm[j]; ctc[q] = g_ctop[j];
            poec[q] = g_pos_e[j]; poic[q] = g_pos_i[j];
            rA[j] = 1.0f / (float)NTOT;
            ncols = q + 1;
        }
    }

    float s = 1.0f;
    const float d = delta[0];
    __syncthreads();
    float *rc = rA, *rn = rB;

    for (int it = 0; it <= WARM; it++) {
        float inv = (s > 0.0f) ? 1.0f / s : 1.0f;

        float sPe[4], sQe[4], sPi[4], sQi[4];
        float ePe = 0, eQe = 0, ePi = 0, eQi = 0;
        if (scanner) {
            float r0 = rc[pe.x], r1 = rc[pe.y], r2 = rc[pe.z], r3 = rc[pe.w];
            sPe[0] = r0 * Ep.x;           sQe[0] = r0 * Em.x;
            sPe[1] = sPe[0] + r1 * Ep.y;  sQe[1] = sQe[0] + r1 * Em.y;
            sPe[2] = sPe[1] + r2 * Ep.z;  sQe[2] = sQe[1] + r2 * Em.z;
            sPe[3] = sPe[2] + r3 * Ep.w;  sQe[3] = sQe[2] + r3 * Em.w;
            float q0 = rc[pi.x], q1 = rc[pi.y], q2 = rc[pi.z], q3 = rc[pi.w];
            sPi[0] = q0 * Ip.x;           sQi[0] = q0 * Im.x;
            sPi[1] = sPi[0] + q1 * Ip.y;  sQi[1] = sQi[0] + q1 * Im.y;
            sPi[2] = sPi[1] + q2 * Ip.z;  sQi[2] = sQi[1] + q2 * Im.z;
            sPi[3] = sPi[2] + q3 * Ip.w;  sQi[3] = sQi[2] + q3 * Im.w;

            float a = sPe[3], b2 = sQe[3], c = sPi[3], d2 = sQi[3];
            #pragma unroll
            for (int o = 1; o < 32; o <<= 1) {
                float ba = __shfl_up_sync(FULL, a, o);
                float bb2 = __shfl_up_sync(FULL, b2, o);
                float bc = __shfl_up_sync(FULL, c, o);
                float bd = __shfl_up_sync(FULL, d2, o);
                if (lane >= o) { a += ba; b2 += bb2; c += bc; d2 += bd; }
            }
            ePe = a - sPe[3]; eQe = b2 - sQe[3];
            ePi = c - sPi[3]; eQi = d2 - sQi[3];
            if (lane == 31) wt4[warp] = make_float4(a, b2, c, d2);
        }
        __syncthreads();                                   // (1)

        if (scanner) {
            float bPe = ePe, bQe = eQe, bPi = ePi, bQi = eQi;
            #pragma unroll 6
            for (int w = 0; w < warp; w++) {
                float4 v = wt4[w];
                bPe += v.x; bQe += v.y; bPi += v.z; bQi += v.w;
            }
            ((float4*)SPe)[seg] = make_float4(bPe + sPe[0], bPe + sPe[1], bPe + sPe[2], bPe + sPe[3]);
            ((float4*)SQe)[seg] = make_float4(bQe + sQe[0], bQe + sQe[1], bQe + sQe[2], bQe + sQe[3]);
            ((float4*)SPi)[seg] = make_float4(bPi + sPi[0], bPi + sPi[1], bPi + sPi[2], bPi + sPi[3]);
            ((float4*)SQi)[seg] = make_float4(bQi + sQi[0], bQi + sQi[1], bQi + sQi[2], bQi + sQi[3]);
        }
        if (t == 224) {
            float a = 0.0f, b2 = 0.0f;
            #pragma unroll
            for (int w = 0; w < 7; w++) { float4 v = wt4[w]; a += v.y; b2 += v.w; }
            tot1 = a; tot3 = b2;
        }
        __syncthreads();                                   // (2)

        float nv = 0.0f;
        #pragma unroll
        for (int q = 0; q < 4; q++) {
            if (q >= ncols) break;
            int j = t + 256 * q;
            int poe = poec[q], poi = poic[q];
            float spe = poe ? SPe[poe - 1] : 0.0f;
            float sqe = poe ? SQe[poe - 1] : 0.0f;
            float spi = poi ? SPi[poi - 1] : 0.0f;
            float sqi = poi ? SQi[poi - 1] : 0.0f;
            float de  = Tmc[q] * spe + Tpc[q] * (tot1 - sqe);
            float di  = Tmc[q] * spi + Tpc[q] * (tot3 - sqi);
            float dot = (de - di) * inv;
            float conc = rc[j] * inv;
            if (it < WARM) {
                float dc = (d / (float)NTOT) * (ctc[q] * (1.0f / (float)NTOT) + dot);
                float v = fmaxf(conc + dc, 0.0f);
                rn[j] = v;
                nv += v;
            } else {
                g_base[j] = conc + (d / (float)NTOT) * dot;
            }
        }
        if (it == WARM) break;

        #pragma unroll
        for (int o = 16; o; o >>= 1) nv += __shfl_xor_sync(FULL, nv, o);
        if (lane == 0) wsum[warp] = nv;
        __syncthreads();                                   // (3)
        if (warp == 0) {
            float v = (lane < 8) ? wsum[lane] : 0.0f;
            #pragma unroll
            for (int o = 4; o; o >>= 1) v += __shfl_xor_sync(FULL, v, o);
            if (lane == 0) s_sh = v;
        }
        __syncthreads();                                   // (4)
        s = s_sh;
        float* tmp = rc; rc = rn; rn = tmp;
    }
}

// =================== k_gemm: R11-exact (64-row tiles, 2 CTAs/SM) ============
#define SMA_H   0                  // 64 rows x 128B
#define SMA_L   8192
#define SMB_H   16384              // 64 rows x 128B
#define SMB_L   24576
#define SMBASE  32768              // 960 floats
#define SMRSUM  (SMBASE + 3840)    // 64 rows x 2 halves
#define SMTOT   (SMRSUM + 512)

__global__ void __launch_bounds__(256, 2)
k_gemm(const float* __restrict__ X, const float* __restrict__ delta,
       float* __restrict__ out) {
    extern __shared__ char sm[];
    const uint32_t sb = smem_u32(sm);
    float* sbase = (float*)(sm + SMBASE);
    float* srsum = (float*)(sm + SMRSUM);
    const int tid = threadIdx.x, wid = tid >> 5, lane = tid & 31;
    const int gr = lane >> 2, tg = lane & 3;
    const int r0 = blockIdx.x * 64;
    const int rg = wid >> 1;
    const int cg = wid & 1;
    const int m0 = rg * 16;

    for (int i = tid; i < NC; i += 256) sbase[i] = g_base[i];

    for (int i = tid; i < 2048; i += 256) {
        int m = i >> 5, c2 = i & 31;
        float2 x = *(const float2*)(X + (size_t)(r0 + m) * 64 + 2 * c2);
        __nv_bfloat162 hp = __floats2bfloat162_rn(x.x, x.y);
        float2 hf = __bfloat1622float2(hp);
        __nv_bfloat162 lp = __floats2bfloat162_rn(x.x - hf.x, x.y - hf.y);
        uint32_t off = SW128((uint32_t)(m * 128 + c2 * 4));
        *(uint32_t*)(sm + SMA_H + off) = *(uint32_t*)&hp;
        *(uint32_t*)(sm + SMA_L + off) = *(uint32_t*)&lp;
    }
    __syncthreads();

    uint32_t ah[4][4], al[4][4];
    {
        int arow = m0 + (lane & 7) + ((lane >> 3) & 1) * 8;
        int acol = (lane >> 4) & 1;
        #pragma unroll
        for (int ks = 0; ks < 4; ks++) {
            uint32_t off = SW128((uint32_t)(arow * 128 + (ks * 2 + acol) * 16));
            LDSM_X4(ah[ks][0], ah[ks][1], ah[ks][2], ah[ks][3], sb + SMA_H + off);
            LDSM_X4(al[ks][0], al[ks][1], al[ks][2], al[ks][3], sb + SMA_L + off);
        }
    }

    const float sc = delta[0] / (float)NTOT;
    float rsLo = 0.0f, rsHi = 0.0f;
    float2 vlo[4], vhi[4];

    const int brow_off = (lane & 7) + ((lane >> 4) & 1) * 8;
    const int bcol_off = (lane >> 3) & 1;

    for (int cc = 0; cc < 15; cc++) {
        #pragma unroll
        for (int q = 0; q < 4; q++) {
            int f = q * 256 + tid;
            int isl = f >> 9;
            int r  = (f & 511) >> 3, ch = f & 7;
            const uint4* src = isl ? (const uint4*)g_Bl : (const uint4*)g_Bh;
            uint4 v = src[(size_t)(cc * 64 + r) * 8 + ch];
            uint32_t off = SW128((uint32_t)(r * 128 + ch * 16));
            *(uint4*)(sm + (isl ? SMB_L : SMB_H) + off) = v;
        }
        __syncthreads();

        float dacc[4][4];
        #pragma unroll
        for (int nt = 0; nt < 4; nt++)
            #pragma unroll
            for (int r = 0; r < 4; r++) dacc[nt][r] = 0.0f;

        #pragma unroll
        for (int ks = 0; ks < 4; ks++) {
            #pragma unroll
            for (int npl = 0; npl < 2; npl++) {
                int np = cg * 2 + npl;
                uint32_t boff = SW128((uint32_t)((np * 16 + brow_off) * 128 +
                                                 (ks * 2 + bcol_off) * 16));
                uint32_t b0, b1, b2, b3;
                LDSM_X4(b0, b1, b2, b3, sb + SMB_H + boff);
                MMA16816(dacc[npl * 2],     ah[ks], b0, b1);
                MMA16816(dacc[npl * 2 + 1], ah[ks], b2, b3);
                MMA16816(dacc[npl * 2],     al[ks], b0, b1);
                MMA16816(dacc[npl * 2 + 1], al[ks], b2, b3);
                LDSM_X4(b0, b1, b2, b3, sb + SMB_L + boff);
                MMA16816(dacc[npl * 2],     ah[ks], b0, b1);
                MMA16816(dacc[npl * 2 + 1], ah[ks], b2, b3);
            }
        }

        #pragma unroll
        for (int nt = 0; nt < 4; nt++) {
            float2 bb = *(const float2*)(sbase + cc * 64 + cg * 32 + nt * 8 + tg * 2);
            float v00 = fmaxf(bb.x + sc * dacc[nt][0], 0.0f);
            float v01 = fmaxf(bb.y + sc * dacc[nt][1], 0.0f);
            float v10 = fmaxf(bb.x + sc * dacc[nt][2], 0.0f);
            float v11 = fmaxf(bb.y + sc * dacc[nt][3], 0.0f);
            rsLo += v00 + v01;
            rsHi += v10 + v11;
            if (cc == 0) { vlo[nt] = make_float2(v00, v01);
                           vhi[nt] = make_float2(v10, v11); }
        }
        __syncthreads();
    }

    rsLo += __shfl_xor_sync(FULL, rsLo, 1);
    rsLo += __shfl_xor_sync(FULL, rsLo, 2);
    rsHi += __shfl_xor_sync(FULL, rsHi, 1);
    rsHi += __shfl_xor_sync(FULL, rsHi, 2);
    if (tg == 0) {
        srsum[(m0 + gr) * 2 + cg]     = rsLo;
        srsum[(m0 + gr + 8) * 2 + cg] = rsHi;
    }
    __syncthreads();

    int rowLo = m0 + gr, rowHi = rowLo + 8;
    float tLo = srsum[rowLo * 2] + srsum[rowLo * 2 + 1];
    float tHi = srsum[rowHi * 2] + srsum[rowHi * 2 + 1];
    float invLo = (tLo > 0.0f) ? 1.0f / tLo : 1.0f;
    float invHi = (tHi > 0.0f) ? 1.0f / tHi : 1.0f;

    #pragma unroll
    for (int nt = 0; nt < 4; nt++) {
        int c = cg * 32 + nt * 8 + tg * 2;
        *(float2*)(out + (size_t)(r0 + rowLo) * 64 + c) =
            make_float2(vlo[nt].x * invLo, vlo[nt].y * invLo);
        *(float2*)(out + (size_t)(r0 + rowHi) * 64 + c) =
            make_float2(vhi[nt].x * invHi, vhi[nt].y * invHi);
    }
}

// ---------------- launch ----------------
extern "C" void kernel_launch(void* const* d_in, const int* in_sizes, int n_in,
                              void* d_out, int out_size) {
    const float* inputs      = (const float*)d_in[0];
    const float* identifiers = (const float*)d_in[1];
    const float* enhancers   = (const float*)d_in[2];
    const float* inhibitors  = (const float*)d_in[3];
    const float* beta        = (const float*)d_in[4];
    const float* delta       = (const float*)d_in[5];
    (void)in_sizes; (void)n_in; (void)out_size;

    cudaFuncSetAttribute(k_gemm, cudaFuncAttributeMaxDynamicSharedMemorySize, SMTOT);

    k_init<<<828, 256>>>(identifiers, enhancers, inhibitors, beta);
    k_warm<<<1, 256>>>(delta);
    k_gemm<<<256, 256, SMTOT>>>(inputs, delta, (float*)d_out);
}

// round 17
// speedup vs baseline: 1.2147x; 1.0034x over previous
#include <cuda_runtime.h>
#include <cuda_bf16.h>
#include <math.h>
#include <stdint.h>

#define NTOT 1024
#define NI   64
#define NC   960
#define NR   896
#define WARM 25
#define FULL 0xffffffffu

// ---------------- device scratch ----------------
__device__ __align__(16) __nv_bfloat16 g_Bh[NC * 64];
__device__ __align__(16) __nv_bfloat16 g_Bl[NC * 64];
__device__ __align__(16) float g_Ep[NR], g_Em[NR], g_Ip[NR], g_Im[NR];
__device__ __align__(16) int   g_pidx_e[NR], g_pidx_i[NR];
__device__ __align__(16) int   g_pos_e[NC], g_pos_i[NC];
__device__ __align__(16) float g_Tp[NC], g_Tm[NC], g_ctop[NC];
__device__ __align__(16) float g_base[NC];

__device__ __forceinline__ uint32_t smem_u32(const void* p) {
    uint32_t a;
    asm("{ .reg .u64 t; cvta.to.shared.u64 t, %1; cvt.u32.u64 %0, t; }" : "=r"(a) : "l"(p));
    return a;
}
#define SW128(x) ((x) ^ (((x) >> 3) & 0x70))

#define LDSM_X4(r0, r1, r2, r3, a) \
    asm volatile("ldmatrix.sync.aligned.m8n8.x4.shared.b16 {%0,%1,%2,%3}, [%4];" \
        : "=r"(r0), "=r"(r1), "=r"(r2), "=r"(r3) : "r"(a))

#define MMA16816(d, a, b0, b1) \
    asm volatile("mma.sync.aligned.m16n8k16.row.col.f32.bf16.bf16.f32 " \
        "{%0,%1,%2,%3}, {%4,%5,%6,%7}, {%8,%9}, {%0,%1,%2,%3};" \
        : "+f"((d)[0]), "+f"((d)[1]), "+f"((d)[2]), "+f"((d)[3]) \
        : "r"((a)[0]), "r"((a)[1]), "r"((a)[2]), "r"((a)[3]), "r"(b0), "r"(b1))

// =================== k_init: R7/R11-exact (828 x 256) ===================
__global__ void k_init(const float* __restrict__ ident, const float* __restrict__ enh,
                       const float* __restrict__ inh,  const float* __restrict__ beta) {
    const int b = blockIdx.x, t = threadIdx.x;
    const int wid = t >> 5, lane = t & 31;
    const float bb = beta[0];

    if (b < 240) {
        int idx = b * 256 + t;
        int j = idx >> 6, k = idx & 63;
        float id = ident[NI + j];
        float v = expf(-bb * fabsf(enh[k] - id)) - expf(-bb * fabsf(inh[k] - id));
        __nv_bfloat16 h = __float2bfloat16(v);
        __nv_bfloat16 l = __float2bfloat16(v - __bfloat162float(h));
        g_Bh[idx] = h;
        g_Bl[idx] = l;
    } else if (b < 464) {
        bool is_e = (b < 352);
        const float* arr = is_e ? enh : inh;
        int k = ((b - (is_e ? 240 : 352)) * 8 + wid);
        float x = arr[128 + k];
        int cnt = 0;
        for (int k2 = lane; k2 < NR; k2 += 32) {
            float y = arr[128 + k2];
            cnt += (y < x) || (y == x && k2 < k);
        }
        #pragma unroll
        for (int o = 16; o; o >>= 1) cnt += __shfl_xor_sync(FULL, cnt, o);
        if (lane == 0) {
            if (is_e) { g_pidx_e[cnt] = k; g_Ep[cnt] = expf(bb * x); g_Em[cnt] = expf(-bb * x); }
            else      { g_pidx_i[cnt] = k; g_Ip[cnt] = expf(bb * x); g_Im[cnt] = expf(-bb * x); }
        }
    } else if (b < 704) {
        bool is_e = (b < 584);
        const float* arr = is_e ? enh : inh;
        int j = ((b - (is_e ? 464 : 584)) * 8 + wid);
        float tj = ident[NI + j];
        int cnt = 0;
        for (int k2 = lane; k2 < NR; k2 += 32) cnt += (arr[128 + k2] <= tj);
        #pragma unroll
        for (int o = 16; o; o >>= 1) cnt += __shfl_xor_sync(FULL, cnt, o);
        if (lane == 0) { if (is_e) g_pos_e[j] = cnt; else g_pos_i[j] = cnt; }
    } else if (b < 824) {
        int j = (b - 704) * 8 + wid;
        float tj = ident[NI + j];
        float c = 0.0f;
        for (int k = lane; k < NI; k += 32)
            c += expf(-bb * fabsf(enh[k] - tj)) - expf(-bb * fabsf(inh[k] - tj));
        #pragma unroll
        for (int o = 16; o; o >>= 1) c += __shfl_xor_sync(FULL, c, o);
        if (lane == 0) g_ctop[j] = c;
    } else {
        int j = (b - 824) * 256 + t;
        if (j < NC) {
            float tj = ident[NI + j];
            g_Tp[j] = expf(bb * tj);
            g_Tm[j] = expf(-bb * tj);
        }
    }
}

// =================== k_warm: 256 threads, merged e/i scanners, 3 bars =======
// scanners: t < 224 (warps 0-6), each owns 4 e-elements AND 4 i-elements.
// consumers: thread t handles columns t, t+256, t+512, t+768 (< 960).
__global__ void __launch_bounds__(256, 1) k_warm(const float* __restrict__ delta) {
    __shared__ float rA[NC], rB[NC];
    __shared__ __align__(16) float SPe[NR], SQe[NR], SPi[NR], SQi[NR];
    __shared__ float4 wt4[8];
    __shared__ __align__(16) float wsum[8];
    __shared__ float tot1, tot3;
    const int t = threadIdx.x, lane = t & 31, warp = t >> 5;

    const bool scanner = (t < 224);
    const int seg = t;

    int4 pe = make_int4(0, 0, 0, 0), pi = pe;
    float4 Ep = make_float4(0, 0, 0, 0), Em = Ep, Ip = Ep, Im = Ep;
    if (scanner) {
        pe = ((const int4*)g_pidx_e)[seg];
        pi = ((const int4*)g_pidx_i)[seg];
        Ep = ((const float4*)g_Ep)[seg];
        Em = ((const float4*)g_Em)[seg];
        Ip = ((const float4*)g_Ip)[seg];
        Im = ((const float4*)g_Im)[seg];
        pe.x += 64; pe.y += 64; pe.z += 64; pe.w += 64;
        pi.x += 64; pi.y += 64; pi.z += 64; pi.w += 64;
    }

    // consumer state: 4 columns j = t + 256*q
    float Tpc[4], Tmc[4], ctc[4];
    int poec[4], poic[4];
    int ncols = 0;
    #pragma unroll
    for (int q = 0; q < 4; q++) {
        int j = t + 256 * q;
        if (j < NC) {
            Tpc[q] = g_Tp[j]; Tmc[q] = g_Tm[j]; ctc[q] = g_ctop[j];
            poec[q] = g_pos_e[j]; poic[q] = g_pos_i[j];
            rA[j] = 1.0f / (float)NTOT;
            ncols = q + 1;
        }
    }

    float s = 1.0f;
    const float d = delta[0];
    __syncthreads();
    float *rc = rA, *rn = rB;

    for (int it = 0; it <= WARM; it++) {
        float inv = (s > 0.0f) ? 1.0f / s : 1.0f;

        float sPe[4], sQe[4], sPi[4], sQi[4];
        float ePe = 0, eQe = 0, ePi = 0, eQi = 0;
        if (scanner) {
            float r0 = rc[pe.x], r1 = rc[pe.y], r2 = rc[pe.z], r3 = rc[pe.w];
            sPe[0] = r0 * Ep.x;           sQe[0] = r0 * Em.x;
            sPe[1] = sPe[0] + r1 * Ep.y;  sQe[1] = sQe[0] + r1 * Em.y;
            sPe[2] = sPe[1] + r2 * Ep.z;  sQe[2] = sQe[1] + r2 * Em.z;
            sPe[3] = sPe[2] + r3 * Ep.w;  sQe[3] = sQe[2] + r3 * Em.w;
            float q0 = rc[pi.x], q1 = rc[pi.y], q2 = rc[pi.z], q3 = rc[pi.w];
            sPi[0] = q0 * Ip.x;           sQi[0] = q0 * Im.x;
            sPi[1] = sPi[0] + q1 * Ip.y;  sQi[1] = sQi[0] + q1 * Im.y;
            sPi[2] = sPi[1] + q2 * Ip.z;  sQi[2] = sQi[1] + q2 * Im.z;
            sPi[3] = sPi[2] + q3 * Ip.w;  sQi[3] = sQi[2] + q3 * Im.w;

            float a = sPe[3], b2 = sQe[3], c = sPi[3], d2 = sQi[3];
            #pragma unroll
            for (int o = 1; o < 32; o <<= 1) {
                float ba = __shfl_up_sync(FULL, a, o);
                float bb2 = __shfl_up_sync(FULL, b2, o);
                float bc = __shfl_up_sync(FULL, c, o);
                float bd = __shfl_up_sync(FULL, d2, o);
                if (lane >= o) { a += ba; b2 += bb2; c += bc; d2 += bd; }
            }
            ePe = a - sPe[3]; eQe = b2 - sQe[3];
            ePi = c - sPi[3]; eQi = d2 - sQi[3];
            if (lane == 31) wt4[warp] = make_float4(a, b2, c, d2);
        }
        __syncthreads();                                   // (1)

        if (scanner) {
            float bPe = ePe, bQe = eQe, bPi = ePi, bQi = eQi;
            #pragma unroll 6
            for (int w = 0; w < warp; w++) {
                float4 v = wt4[w];
                bPe += v.x; bQe += v.y; bPi += v.z; bQi += v.w;
            }
            ((float4*)SPe)[seg] = make_float4(bPe + sPe[0], bPe + sPe[1], bPe + sPe[2], bPe + sPe[3]);
            ((float4*)SQe)[seg] = make_float4(bQe + sQe[0], bQe + sQe[1], bQe + sQe[2], bQe + sQe[3]);
            ((float4*)SPi)[seg] = make_float4(bPi + sPi[0], bPi + sPi[1], bPi + sPi[2], bPi + sPi[3]);
            ((float4*)SQi)[seg] = make_float4(bQi + sQi[0], bQi + sQi[1], bQi + sQi[2], bQi + sQi[3]);
        }
        if (t == 224) {
            float a = 0.0f, b2 = 0.0f;
            #pragma unroll
            for (int w = 0; w < 7; w++) { float4 v = wt4[w]; a += v.y; b2 += v.w; }
            tot1 = a; tot3 = b2;
        }
        __syncthreads();                                   // (2)

        float nv = 0.0f;
        #pragma unroll
        for (int q = 0; q < 4; q++) {
            if (q >= ncols) break;
            int j = t + 256 * q;
            int poe = poec[q], poi = poic[q];
            float spe = poe ? SPe[poe - 1] : 0.0f;
            float sqe = poe ? SQe[poe - 1] : 0.0f;
            float spi = poi ? SPi[poi - 1] : 0.0f;
            float sqi = poi ? SQi[poi - 1] : 0.0f;
            float de  = Tmc[q] * spe + Tpc[q] * (tot1 - sqe);
            float di  = Tmc[q] * spi + Tpc[q] * (tot3 - sqi);
            float dot = (de - di) * inv;
            float conc = rc[j] * inv;
            if (it < WARM) {
                float dc = (d / (float)NTOT) * (ctc[q] * (1.0f / (float)NTOT) + dot);
                float v = fmaxf(conc + dc, 0.0f);
                rn[j] = v;
                nv += v;
            } else {
                g_base[j] = conc + (d / (float)NTOT) * dot;
            }
        }
        if (it == WARM) break;

        #pragma unroll
        for (int o = 16; o; o >>= 1) nv += __shfl_xor_sync(FULL, nv, o);
        if (lane == 0) wsum[warp] = nv;
        __syncthreads();                                   // (3): rn + wsum visible

        // every warp redundantly reduces the 8 wsum entries (same tree order
        // as the old warp-0 reduce -> bitwise-identical s); no 4th barrier.
        {
            float v = (lane < 8) ? wsum[lane] : 0.0f;
            #pragma unroll
            for (int o = 4; o; o >>= 1) v += __shfl_xor_sync(FULL, v, o);
            s = __shfl_sync(FULL, v, 0);
        }
        float* tmp = rc; rc = rn; rn = tmp;
    }
}

// =================== k_gemm: R11-exact (64-row tiles, 2 CTAs/SM) ============
#define SMA_H   0                  // 64 rows x 128B
#define SMA_L   8192
#define SMB_H   16384              // 64 rows x 128B
#define SMB_L   24576
#define SMBASE  32768              // 960 floats
#define SMRSUM  (SMBASE + 3840)    // 64 rows x 2 halves
#define SMTOT   (SMRSUM + 512)

__global__ void __launch_bounds__(256, 2)
k_gemm(const float* __restrict__ X, const float* __restrict__ delta,
       float* __restrict__ out) {
    extern __shared__ char sm[];
    const uint32_t sb = smem_u32(sm);
    float* sbase = (float*)(sm + SMBASE);
    float* srsum = (float*)(sm + SMRSUM);
    const int tid = threadIdx.x, wid = tid >> 5, lane = tid & 31;
    const int gr = lane >> 2, tg = lane & 3;
    const int r0 = blockIdx.x * 64;
    const int rg = wid >> 1;
    const int cg = wid & 1;
    const int m0 = rg * 16;

    for (int i = tid; i < NC; i += 256) sbase[i] = g_base[i];

    for (int i = tid; i < 2048; i += 256) {
        int m = i >> 5, c2 = i & 31;
        float2 x = *(const float2*)(X + (size_t)(r0 + m) * 64 + 2 * c2);
        __nv_bfloat162 hp = __floats2bfloat162_rn(x.x, x.y);
        float2 hf = __bfloat1622float2(hp);
        __nv_bfloat162 lp = __floats2bfloat162_rn(x.x - hf.x, x.y - hf.y);
        uint32_t off = SW128((uint32_t)(m * 128 + c2 * 4));
        *(uint32_t*)(sm + SMA_H + off) = *(uint32_t*)&hp;
        *(uint32_t*)(sm + SMA_L + off) = *(uint32_t*)&lp;
    }
    __syncthreads();

    uint32_t ah[4][4], al[4][4];
    {
        int arow = m0 + (lane & 7) + ((lane >> 3) & 1) * 8;
        int acol = (lane >> 4) & 1;
        #pragma unroll
        for (int ks = 0; ks < 4; ks++) {
            uint32_t off = SW128((uint32_t)(arow * 128 + (ks * 2 + acol) * 16));
            LDSM_X4(ah[ks][0], ah[ks][1], ah[ks][2], ah[ks][3], sb + SMA_H + off);
            LDSM_X4(al[ks][0], al[ks][1], al[ks][2], al[ks][3], sb + SMA_L + off);
        }
    }

    const float sc = delta[0] / (float)NTOT;
    float rsLo = 0.0f, rsHi = 0.0f;
    float2 vlo[4], vhi[4];

    const int brow_off = (lane & 7) + ((lane >> 4) & 1) * 8;
    const int bcol_off = (lane >> 3) & 1;

    for (int cc = 0; cc < 15; cc++) {
        #pragma unroll
        for (int q = 0; q < 4; q++) {
            int f = q * 256 + tid;
            int isl = f >> 9;
            int r  = (f & 511) >> 3, ch = f & 7;
            const uint4* src = isl ? (const uint4*)g_Bl : (const uint4*)g_Bh;
            uint4 v = src[(size_t)(cc * 64 + r) * 8 + ch];
            uint32_t off = SW128((uint32_t)(r * 128 + ch * 16));
            *(uint4*)(sm + (isl ? SMB_L : SMB_H) + off) = v;
        }
        __syncthreads();

        float dacc[4][4];
        #pragma unroll
        for (int nt = 0; nt < 4; nt++)
            #pragma unroll
            for (int r = 0; r < 4; r++) dacc[nt][r] = 0.0f;

        #pragma unroll
        for (int ks = 0; ks < 4; ks++) {
            #pragma unroll
            for (int npl = 0; npl < 2; npl++) {
                int np = cg * 2 + npl;
                uint32_t boff = SW128((uint32_t)((np * 16 + brow_off) * 128 +
                                                 (ks * 2 + bcol_off) * 16));
                uint32_t b0, b1, b2, b3;
                LDSM_X4(b0, b1, b2, b3, sb + SMB_H + boff);
                MMA16816(dacc[npl * 2],     ah[ks], b0, b1);
                MMA16816(dacc[npl * 2 + 1], ah[ks], b2, b3);
                MMA16816(dacc[npl * 2],     al[ks], b0, b1);
                MMA16816(dacc[npl * 2 + 1], al[ks], b2, b3);
                LDSM_X4(b0, b1, b2, b3, sb + SMB_L + boff);
                MMA16816(dacc[npl * 2],     ah[ks], b0, b1);
                MMA16816(dacc[npl * 2 + 1], ah[ks], b2, b3);
            }
        }

        #pragma unroll
        for (int nt = 0; nt < 4; nt++) {
            float2 bb = *(const float2*)(sbase + cc * 64 + cg * 32 + nt * 8 + tg * 2);
            float v00 = fmaxf(bb.x + sc * dacc[nt][0], 0.0f);
            float v01 = fmaxf(bb.y + sc * dacc[nt][1], 0.0f);
            float v10 = fmaxf(bb.x + sc * dacc[nt][2], 0.0f);
            float v11 = fmaxf(bb.y + sc * dacc[nt][3], 0.0f);
            rsLo += v00 + v01;
            rsHi += v10 + v11;
            if (cc == 0) { vlo[nt] = make_float2(v00, v01);
                           vhi[nt] = make_float2(v10, v11); }
        }
        __syncthreads();
    }

    rsLo += __shfl_xor_sync(FULL, rsLo, 1);
    rsLo += __shfl_xor_sync(FULL, rsLo, 2);
    rsHi += __shfl_xor_sync(FULL, rsHi, 1);
    rsHi += __shfl_xor_sync(FULL, rsHi, 2);
    if (tg == 0) {
        srsum[(m0 + gr) * 2 + cg]     = rsLo;
        srsum[(m0 + gr + 8) * 2 + cg] = rsHi;
    }
    __syncthreads();

    int rowLo = m0 + gr, rowHi = rowLo + 8;
    float tLo = srsum[rowLo * 2] + srsum[rowLo * 2 + 1];
    float tHi = srsum[rowHi * 2] + srsum[rowHi * 2 + 1];
    float invLo = (tLo > 0.0f) ? 1.0f / tLo : 1.0f;
    float invHi = (tHi > 0.0f) ? 1.0f / tHi : 1.0f;

    #pragma unroll
    for (int nt = 0; nt < 4; nt++) {
        int c = cg * 32 + nt * 8 + tg * 2;
        *(float2*)(out + (size_t)(r0 + rowLo) * 64 + c) =
            make_float2(vlo[nt].x * invLo, vlo[nt].y * invLo);
        *(float2*)(out + (size_t)(r0 + rowHi) * 64 + c) =
            make_float2(vhi[nt].x * invHi, vhi[nt].y * invHi);
    }
}

// ---------------- launch ----------------
extern "C" void kernel_launch(void* const* d_in, const int* in_sizes, int n_in,
                              void* d_out, int out_size) {
    const float* inputs      = (const float*)d_in[0];
    const float* identifiers = (const float*)d_in[1];
    const float* enhancers   = (const float*)d_in[2];
    const float* inhibitors  = (const float*)d_in[3];
    const float* beta        = (const float*)d_in[4];
    const float* delta       = (const float*)d_in[5];
    (void)in_sizes; (void)n_in; (void)out_size;

    cudaFuncSetAttribute(k_gemm, cudaFuncAttributeMaxDynamicSharedMemorySize, SMTOT);

    k_init<<<828, 256>>>(identifiers, enhancers, inhibitors, beta);
    k_warm<<<1, 256>>>(delta);
    k_gemm<<<256, 256, SMTOT>>>(inputs, delta, (float*)d_out);
}